// round 1
// baseline (speedup 1.0000x reference)
#include <cuda_runtime.h>

// ---------------- problem constants (fixed by setup_inputs) ----------------
#define NN   50000
#define EE   800000
#define F0   128
#define NHEAD 4
#define C1   64
#define F1   (NHEAD*C1)   // 256
#define C2   16
#define F2   (NHEAD*C2)   // 64
#define NG   64
#define NOUT 32
#define NEG_SLOPE 0.2f

// ---------------- scratch (device globals; no allocation allowed) ----------
__device__ float d_h1[NN*F1];          // layer1 pre-agg features  (51.2 MB)
__device__ float d_g1[NN*F1];          // layer1 aggregated        (51.2 MB)
__device__ float d_h2[NN*F2];          // layer2 pre-agg features  (12.8 MB)
__device__ float d_g2[NN*F2];          // layer2 aggregated        (12.8 MB)
__device__ float d_as[NN*NHEAD];       // alpha_src per node/head
__device__ float d_ad[NN*NHEAD];       // alpha_dst per node/head
__device__ float d_ns[NN*NHEAD];       // softmax denom (then reciprocal)
__device__ float d_wb[(EE+NN)*NHEAD];  // exp(e) per edge/head     (13.6 MB)
__device__ float d_pool[NG*F2];
__device__ float d_cnt[NG];

// ---------------- vector reduction helper ----------------------------------
__device__ __forceinline__ void red_add_v4(float* p, float4 v) {
    asm volatile("red.global.add.v4.f32 [%0], {%1,%2,%3,%4};"
                 :: "l"(p), "f"(v.x), "f"(v.y), "f"(v.z), "f"(v.w) : "memory");
}

// ---------------- tiled SGEMM: C[M,N] = A[M,K] @ B[K,N] --------------------
// 64x64 tile, TK=16, 256 threads, 4x4 register micro-tile. K % 16 == 0, N % 64 == 0.
__global__ void sgemm64(const float* __restrict__ A, const float* __restrict__ B,
                        float* __restrict__ C, int M, int N, int K) {
    __shared__ float As[16][64];
    __shared__ float Bs[16][64];
    int tid = threadIdx.x;
    int tx = tid & 15, ty = tid >> 4;
    int m0 = blockIdx.x * 64;
    int n0 = blockIdx.y * 64;

    float acc[4][4];
#pragma unroll
    for (int i = 0; i < 4; i++)
#pragma unroll
        for (int j = 0; j < 4; j++) acc[i][j] = 0.f;

    int lm  = tid >> 2;         // 0..63 : A row within tile
    int lk  = (tid & 3) * 4;    // 0,4,8,12 : A k offset
    int lbk = tid >> 4;         // 0..15 : B k row
    int lbn = (tid & 15) * 4;   // 0..60 : B col offset

    for (int k0 = 0; k0 < K; k0 += 16) {
        float4 av = make_float4(0.f, 0.f, 0.f, 0.f);
        int am = m0 + lm;
        if (am < M)
            av = *reinterpret_cast<const float4*>(&A[(size_t)am * K + k0 + lk]);
        As[lk + 0][lm] = av.x; As[lk + 1][lm] = av.y;
        As[lk + 2][lm] = av.z; As[lk + 3][lm] = av.w;

        float4 bv = *reinterpret_cast<const float4*>(&B[(size_t)(k0 + lbk) * N + n0 + lbn]);
        *reinterpret_cast<float4*>(&Bs[lbk][lbn]) = bv;
        __syncthreads();

#pragma unroll
        for (int kk = 0; kk < 16; kk++) {
            float4 a = *reinterpret_cast<float4*>(&As[kk][ty * 4]);
            float4 b = *reinterpret_cast<float4*>(&Bs[kk][tx * 4]);
            acc[0][0] += a.x * b.x; acc[0][1] += a.x * b.y; acc[0][2] += a.x * b.z; acc[0][3] += a.x * b.w;
            acc[1][0] += a.y * b.x; acc[1][1] += a.y * b.y; acc[1][2] += a.y * b.z; acc[1][3] += a.y * b.w;
            acc[2][0] += a.z * b.x; acc[2][1] += a.z * b.y; acc[2][2] += a.z * b.z; acc[2][3] += a.z * b.w;
            acc[3][0] += a.w * b.x; acc[3][1] += a.w * b.y; acc[3][2] += a.w * b.z; acc[3][3] += a.w * b.w;
        }
        __syncthreads();
    }

#pragma unroll
    for (int i = 0; i < 4; i++) {
        int m = m0 + ty * 4 + i;
        if (m < M) {
            float4 o = make_float4(acc[i][0], acc[i][1], acc[i][2], acc[i][3]);
            *reinterpret_cast<float4*>(&C[(size_t)m * N + n0 + tx * 4]) = o;
        }
    }
}

// ---------------- per-node attention logits: alpha_s / alpha_d -------------
template<int C>
__global__ void alpha_kernel(const float* __restrict__ h,
                             const float* __restrict__ asr, const float* __restrict__ adt,
                             float* __restrict__ outs, float* __restrict__ outd, int N) {
    int idx = blockIdx.x * blockDim.x + threadIdx.x;
    if (idx >= N * NHEAD) return;
    int hh = idx & (NHEAD - 1);
    const float* hp = h + (size_t)idx * C;       // (n*NHEAD + hh) * C
    const float* ap = asr + hh * C;
    const float* dp = adt + hh * C;
    float ss = 0.f, dd = 0.f;
#pragma unroll
    for (int i = 0; i < C; i += 4) {
        float4 v = *reinterpret_cast<const float4*>(hp + i);
        float4 a = *reinterpret_cast<const float4*>(ap + i);
        float4 d = *reinterpret_cast<const float4*>(dp + i);
        ss += v.x * a.x + v.y * a.y + v.z * a.z + v.w * a.w;
        dd += v.x * d.x + v.y * d.y + v.z * d.z + v.w * d.w;
    }
    outs[idx] = ss;
    outd[idx] = dd;
}

// ---------------- edge pass 1: w = exp(leaky_relu(as[s]+ad[d])), denom -----
__global__ void edge_sum_kernel(const int* __restrict__ ei,
                                const float* __restrict__ as, const float* __restrict__ ad,
                                float* __restrict__ wbuf, float* __restrict__ nsum,
                                int E, int N) {
    int e = blockIdx.x * blockDim.x + threadIdx.x;
    if (e >= E + N) return;
    int s, d;
    if (e < E) { s = ei[e]; d = ei[E + e]; } else { s = d = e - E; }
    float4 a = *reinterpret_cast<const float4*>(as + (size_t)s * 4);
    float4 b = *reinterpret_cast<const float4*>(ad + (size_t)d * 4);
    float4 w;
    float t;
    t = a.x + b.x; t = t > 0.f ? t : NEG_SLOPE * t; w.x = __expf(t);
    t = a.y + b.y; t = t > 0.f ? t : NEG_SLOPE * t; w.y = __expf(t);
    t = a.z + b.z; t = t > 0.f ? t : NEG_SLOPE * t; w.z = __expf(t);
    t = a.w + b.w; t = t > 0.f ? t : NEG_SLOPE * t; w.w = __expf(t);
    *reinterpret_cast<float4*>(wbuf + (size_t)e * 4) = w;
    red_add_v4(nsum + (size_t)d * 4, w);
}

__global__ void recip_kernel(float* __restrict__ x, int n) {
    int i = blockIdx.x * blockDim.x + threadIdx.x;
    if (i < n) x[i] = 1.0f / x[i];
}

// ---------------- edge pass 2: out[d] += (w/denom[d]) * h[s] ---------------
template<int C>
__global__ void edge_agg_kernel(const int* __restrict__ ei,
                                const float* __restrict__ wbuf, const float* __restrict__ ninv,
                                const float* __restrict__ h, float* __restrict__ out,
                                int E, int N) {
    const int Q = C / 4;
    int idx = blockIdx.x * blockDim.x + threadIdx.x;
    int total = (E + N) * NHEAD * Q;
    if (idx >= total) return;
    int q  = idx % Q;
    int hh = (idx / Q) & (NHEAD - 1);
    int e  = idx / (Q * NHEAD);
    int s, d;
    if (e < E) { s = ei[e]; d = ei[E + e]; } else { s = d = e - E; }
    float w = wbuf[(size_t)e * NHEAD + hh] * ninv[(size_t)d * NHEAD + hh];
    float4 v = *reinterpret_cast<const float4*>(h + ((size_t)s * NHEAD + hh) * C + q * 4);
    float4 r = make_float4(w * v.x, w * v.y, w * v.z, w * v.w);
    red_add_v4(out + ((size_t)d * NHEAD + hh) * C + q * 4, r);
}

// ---------------- bias + relu ----------------------------------------------
__global__ void bias_relu_kernel(float* __restrict__ g, const float* __restrict__ b,
                                 int n, int Fmask) {
    int i = blockIdx.x * blockDim.x + threadIdx.x;
    if (i >= n) return;
    float v = g[i] + b[i & Fmask];   // F is power of two
    g[i] = v > 0.f ? v : 0.f;
}

// ---------------- pooling (batch sorted -> run-length local accumulation) --
__global__ void pool_kernel(const float* __restrict__ g, const int* __restrict__ batch,
                            float* __restrict__ pool, int N) {
    int c = blockIdx.y;
    int t = blockIdx.x * blockDim.x + threadIdx.x;
    const int CH = 64;
    int n0 = t * CH;
    if (n0 >= N) return;
    int n1 = min(N, n0 + CH);
    int cur = batch[n0];
    float acc = 0.f;
    for (int n = n0; n < n1; n++) {
        int bb = batch[n];
        if (bb != cur) { atomicAdd(&pool[cur * F2 + c], acc); cur = bb; acc = 0.f; }
        acc += g[(size_t)n * F2 + c];
    }
    atomicAdd(&pool[cur * F2 + c], acc);
}

__global__ void count_kernel(const int* __restrict__ batch, float* __restrict__ cnt, int N) {
    int t = blockIdx.x * blockDim.x + threadIdx.x;
    const int CH = 64;
    int n0 = t * CH;
    if (n0 >= N) return;
    int n1 = min(N, n0 + CH);
    int cur = batch[n0];
    float acc = 0.f;
    for (int n = n0; n < n1; n++) {
        int bb = batch[n];
        if (bb != cur) { atomicAdd(&cnt[cur], acc); cur = bb; acc = 0.f; }
        acc += 1.f;
    }
    atomicAdd(&cnt[cur], acc);
}

// ---------------- final FC: out[g] = mean_pool[g] @ fc_w + fc_b ------------
__global__ void fc_kernel(const float* __restrict__ pool, const float* __restrict__ cnt,
                          const float* __restrict__ w, const float* __restrict__ b,
                          float* __restrict__ out) {
    int g = blockIdx.x;
    int j = threadIdx.x;   // 0..31
    float inv = 1.f / fmaxf(cnt[g], 1.f);
    float acc = b[j];
#pragma unroll
    for (int c = 0; c < F2; c++)
        acc += pool[g * F2 + c] * inv * w[c * NOUT + j];
    out[g * NOUT + j] = acc;
}

// ---------------- launch ----------------------------------------------------
extern "C" void kernel_launch(void* const* d_in, const int* in_sizes, int n_in,
                              void* d_out, int out_size) {
    const float* x      = (const float*)d_in[0];
    const int*   ei     = (const int*)  d_in[1];
    const int*   batch  = (const int*)  d_in[2];
    const float* W1     = (const float*)d_in[3];
    const float* a_src1 = (const float*)d_in[4];
    const float* a_dst1 = (const float*)d_in[5];
    const float* b1     = (const float*)d_in[6];
    const float* W2     = (const float*)d_in[7];
    const float* a_src2 = (const float*)d_in[8];
    const float* a_dst2 = (const float*)d_in[9];
    const float* b2     = (const float*)d_in[10];
    const float* fcw    = (const float*)d_in[11];
    const float* fcb    = (const float*)d_in[12];

    int N = in_sizes[0] / F0;     // 50000
    int E = in_sizes[1] / 2;      // 800000
    int ET = E + N;

    float *p_h1, *p_g1, *p_h2, *p_g2, *p_as, *p_ad, *p_ns, *p_wb, *p_pool, *p_cnt;
    cudaGetSymbolAddress((void**)&p_h1, d_h1);
    cudaGetSymbolAddress((void**)&p_g1, d_g1);
    cudaGetSymbolAddress((void**)&p_h2, d_h2);
    cudaGetSymbolAddress((void**)&p_g2, d_g2);
    cudaGetSymbolAddress((void**)&p_as, d_as);
    cudaGetSymbolAddress((void**)&p_ad, d_ad);
    cudaGetSymbolAddress((void**)&p_ns, d_ns);
    cudaGetSymbolAddress((void**)&p_wb, d_wb);
    cudaGetSymbolAddress((void**)&p_pool, d_pool);
    cudaGetSymbolAddress((void**)&p_cnt, d_cnt);

    float* out = (float*)d_out;

    // ---------------- layer 1 ----------------
    {
        dim3 grid((N + 63) / 64, F1 / 64);
        sgemm64<<<grid, 256>>>(x, W1, p_h1, N, F1, F0);
    }
    alpha_kernel<C1><<<(N * NHEAD + 255) / 256, 256>>>(p_h1, a_src1, a_dst1, p_as, p_ad, N);
    cudaMemsetAsync(p_ns, 0, (size_t)N * NHEAD * sizeof(float));
    edge_sum_kernel<<<(ET + 255) / 256, 256>>>(ei, p_as, p_ad, p_wb, p_ns, E, N);
    recip_kernel<<<(N * NHEAD + 255) / 256, 256>>>(p_ns, N * NHEAD);
    cudaMemsetAsync(p_g1, 0, (size_t)N * F1 * sizeof(float));
    {
        int total = ET * NHEAD * (C1 / 4);
        edge_agg_kernel<C1><<<(total + 255) / 256, 256>>>(ei, p_wb, p_ns, p_h1, p_g1, E, N);
    }
    bias_relu_kernel<<<((size_t)N * F1 + 255) / 256, 256>>>(p_g1, b1, N * F1, F1 - 1);

    // ---------------- layer 2 ----------------
    {
        dim3 grid((N + 63) / 64, F2 / 64);
        sgemm64<<<grid, 256>>>(p_g1, W2, p_h2, N, F2, F1);
    }
    alpha_kernel<C2><<<(N * NHEAD + 255) / 256, 256>>>(p_h2, a_src2, a_dst2, p_as, p_ad, N);
    cudaMemsetAsync(p_ns, 0, (size_t)N * NHEAD * sizeof(float));
    edge_sum_kernel<<<(ET + 255) / 256, 256>>>(ei, p_as, p_ad, p_wb, p_ns, E, N);
    recip_kernel<<<(N * NHEAD + 255) / 256, 256>>>(p_ns, N * NHEAD);
    cudaMemsetAsync(p_g2, 0, (size_t)N * F2 * sizeof(float));
    {
        int total = ET * NHEAD * (C2 / 4);
        edge_agg_kernel<C2><<<(total + 255) / 256, 256>>>(ei, p_wb, p_ns, p_h2, p_g2, E, N);
    }
    bias_relu_kernel<<<((size_t)N * F2 + 255) / 256, 256>>>(p_g2, b2, N * F2, F2 - 1);

    // ---------------- pooling + FC ----------------
    cudaMemsetAsync(p_pool, 0, (size_t)NG * F2 * sizeof(float));
    cudaMemsetAsync(p_cnt, 0, (size_t)NG * sizeof(float));
    {
        int nthreads = (N + 63) / 64;
        dim3 grid((nthreads + 127) / 128, F2);
        pool_kernel<<<grid, 128>>>(p_g2, batch, p_pool, N);
        count_kernel<<<(nthreads + 127) / 128, 128>>>(batch, p_cnt, N);
    }
    fc_kernel<<<NG, NOUT>>>(p_pool, p_cnt, fcw, fcb, out);
}

// round 2
// speedup vs baseline: 1.2070x; 1.2070x over previous
#include <cuda_runtime.h>

// ---------------- problem constants (fixed by setup_inputs) ----------------
#define NN   50000
#define EE   800000
#define ET_MAX (EE+NN)
#define F0   128
#define NHEAD 4
#define C1   64
#define F1   (NHEAD*C1)   // 256
#define C2   16
#define F2   (NHEAD*C2)   // 64
#define NG   64
#define NOUT 32
#define NEG_SLOPE 0.2f

// ---------------- scratch (device globals; no allocation allowed) ----------
__device__ float d_h1[NN*F1];          // layer1 pre-agg features
__device__ float d_g1[NN*F1];          // layer1 aggregated
__device__ float d_h2[NN*F2];          // layer2 pre-agg features
__device__ float d_g2[NN*F2];          // layer2 aggregated
__device__ float d_as[NN*NHEAD];       // alpha_src per node/head
__device__ float d_ad[NN*NHEAD];       // alpha_dst per node/head
__device__ float d_ni[NN*NHEAD];       // 1/softmax-denominator
__device__ int   d_deg[NN];            // per-dst degree histogram
__device__ int   d_rowptr[NN+1];       // CSR row pointers (by dst)
__device__ int   d_rowpos[NN];         // scatter fill cursors
__device__ int   d_csrsrc[ET_MAX];     // src node per dst-sorted edge
__device__ float d_pool[NG*F2];
__device__ float d_cnt[NG];

// ---------------- tiled SGEMM: C[M,N] = A[M,K] @ B[K,N] --------------------
__global__ void sgemm64(const float* __restrict__ A, const float* __restrict__ B,
                        float* __restrict__ C, int M, int N, int K) {
    __shared__ float As[16][64];
    __shared__ float Bs[16][64];
    int tid = threadIdx.x;
    int tx = tid & 15, ty = tid >> 4;
    int m0 = blockIdx.x * 64;
    int n0 = blockIdx.y * 64;

    float acc[4][4];
#pragma unroll
    for (int i = 0; i < 4; i++)
#pragma unroll
        for (int j = 0; j < 4; j++) acc[i][j] = 0.f;

    int lm  = tid >> 2;
    int lk  = (tid & 3) * 4;
    int lbk = tid >> 4;
    int lbn = (tid & 15) * 4;

    for (int k0 = 0; k0 < K; k0 += 16) {
        float4 av = make_float4(0.f, 0.f, 0.f, 0.f);
        int am = m0 + lm;
        if (am < M)
            av = *reinterpret_cast<const float4*>(&A[(size_t)am * K + k0 + lk]);
        As[lk + 0][lm] = av.x; As[lk + 1][lm] = av.y;
        As[lk + 2][lm] = av.z; As[lk + 3][lm] = av.w;

        float4 bv = *reinterpret_cast<const float4*>(&B[(size_t)(k0 + lbk) * N + n0 + lbn]);
        *reinterpret_cast<float4*>(&Bs[lbk][lbn]) = bv;
        __syncthreads();

#pragma unroll
        for (int kk = 0; kk < 16; kk++) {
            float4 a = *reinterpret_cast<float4*>(&As[kk][ty * 4]);
            float4 b = *reinterpret_cast<float4*>(&Bs[kk][tx * 4]);
            acc[0][0] += a.x * b.x; acc[0][1] += a.x * b.y; acc[0][2] += a.x * b.z; acc[0][3] += a.x * b.w;
            acc[1][0] += a.y * b.x; acc[1][1] += a.y * b.y; acc[1][2] += a.y * b.z; acc[1][3] += a.y * b.w;
            acc[2][0] += a.z * b.x; acc[2][1] += a.z * b.y; acc[2][2] += a.z * b.z; acc[2][3] += a.z * b.w;
            acc[3][0] += a.w * b.x; acc[3][1] += a.w * b.y; acc[3][2] += a.w * b.z; acc[3][3] += a.w * b.w;
        }
        __syncthreads();
    }

#pragma unroll
    for (int i = 0; i < 4; i++) {
        int m = m0 + ty * 4 + i;
        if (m < M) {
            float4 o = make_float4(acc[i][0], acc[i][1], acc[i][2], acc[i][3]);
            *reinterpret_cast<float4*>(&C[(size_t)m * N + n0 + tx * 4]) = o;
        }
    }
}

// ---------------- CSR build: histogram -> scan -> scatter -------------------
__global__ void hist_kernel(const int* __restrict__ ei, int* __restrict__ deg,
                            int E, int N) {
    int e = blockIdx.x * blockDim.x + threadIdx.x;
    if (e >= E + N) return;
    int d = (e < E) ? ei[E + e] : (e - E);
    atomicAdd(&deg[d], 1);
}

__global__ void scan_kernel(const int* __restrict__ deg, int* __restrict__ rowptr,
                            int* __restrict__ rowpos, int N) {
    __shared__ int sums[1024];
    int t = threadIdx.x;
    int CH = (N + 1023) / 1024;
    int b = t * CH, e = min(N, b + CH);
    int s = 0;
    for (int i = b; i < e; i++) s += deg[i];
    sums[t] = s;
    __syncthreads();
    for (int off = 1; off < 1024; off <<= 1) {
        int v = (t >= off) ? sums[t - off] : 0;
        __syncthreads();
        sums[t] += v;
        __syncthreads();
    }
    int run = (t == 0) ? 0 : sums[t - 1];
    for (int i = b; i < e; i++) {
        rowptr[i] = run;
        rowpos[i] = run;
        run += deg[i];
    }
    if (t == 1023) rowptr[N] = sums[1023];
}

__global__ void scatter_kernel(const int* __restrict__ ei, int* __restrict__ rowpos,
                               int* __restrict__ csrsrc, int E, int N) {
    int e = blockIdx.x * blockDim.x + threadIdx.x;
    if (e >= E + N) return;
    int s, d;
    if (e < E) { s = ei[e]; d = ei[E + e]; } else { s = d = e - E; }
    int pos = atomicAdd(&rowpos[d], 1);
    csrsrc[pos] = s;
}

// ---------------- per-node attention logits --------------------------------
template<int C>
__global__ void alpha_kernel(const float* __restrict__ h,
                             const float* __restrict__ asr, const float* __restrict__ adt,
                             float* __restrict__ outs, float* __restrict__ outd, int N) {
    int idx = blockIdx.x * blockDim.x + threadIdx.x;
    if (idx >= N * NHEAD) return;
    int hh = idx & (NHEAD - 1);
    const float* hp = h + (size_t)idx * C;
    const float* ap = asr + hh * C;
    const float* dp = adt + hh * C;
    float ss = 0.f, dd = 0.f;
#pragma unroll
    for (int i = 0; i < C; i += 4) {
        float4 v = *reinterpret_cast<const float4*>(hp + i);
        float4 a = *reinterpret_cast<const float4*>(ap + i);
        float4 d = *reinterpret_cast<const float4*>(dp + i);
        ss += v.x * a.x + v.y * a.y + v.z * a.z + v.w * a.w;
        dd += v.x * d.x + v.y * d.y + v.z * d.z + v.w * d.w;
    }
    outs[idx] = ss;
    outd[idx] = dd;
}

// ---------------- pull-based softmax denominator (warp per dst node) -------
__global__ void denom_kernel(const int* __restrict__ rowptr, const int* __restrict__ csrsrc,
                             const float* __restrict__ as, const float* __restrict__ ad,
                             float* __restrict__ ninv, int N) {
    int gw = (blockIdx.x * blockDim.x + threadIdx.x) >> 5;
    int lane = threadIdx.x & 31;
    if (gw >= N) return;
    int beg = rowptr[gw], end = rowptr[gw + 1];
    float4 ad4 = *reinterpret_cast<const float4*>(ad + (size_t)gw * 4);
    float s0 = 0.f, s1 = 0.f, s2 = 0.f, s3 = 0.f;
    for (int i = beg + lane; i < end; i += 32) {
        int s = csrsrc[i];
        float4 a = *reinterpret_cast<const float4*>(as + (size_t)s * 4);
        float t;
        t = a.x + ad4.x; t = t > 0.f ? t : NEG_SLOPE * t; s0 += __expf(t);
        t = a.y + ad4.y; t = t > 0.f ? t : NEG_SLOPE * t; s1 += __expf(t);
        t = a.z + ad4.z; t = t > 0.f ? t : NEG_SLOPE * t; s2 += __expf(t);
        t = a.w + ad4.w; t = t > 0.f ? t : NEG_SLOPE * t; s3 += __expf(t);
    }
#pragma unroll
    for (int off = 16; off; off >>= 1) {
        s0 += __shfl_xor_sync(0xffffffffu, s0, off);
        s1 += __shfl_xor_sync(0xffffffffu, s1, off);
        s2 += __shfl_xor_sync(0xffffffffu, s2, off);
        s3 += __shfl_xor_sync(0xffffffffu, s3, off);
    }
    if (lane == 0) {
        float4 r = make_float4(1.f / s0, 1.f / s1, 1.f / s2, 1.f / s3);
        *reinterpret_cast<float4*>(ninv + (size_t)gw * 4) = r;
    }
}

// ---------------- pull aggregation layer 1 (warp per (dst, head)) ----------
// C1=64: each lane owns 2 channels. Fused bias + relu epilogue.
__global__ void agg1_kernel(const int* __restrict__ rowptr, const int* __restrict__ csrsrc,
                            const float* __restrict__ as, const float* __restrict__ ad,
                            const float* __restrict__ ninv, const float* __restrict__ h,
                            const float* __restrict__ bias, float* __restrict__ out, int N) {
    int gw = (blockIdx.x * blockDim.x + threadIdx.x) >> 5;
    int lane = threadIdx.x & 31;
    if (gw >= N * NHEAD) return;
    int n = gw >> 2, hh = gw & 3;
    int beg = rowptr[n], end = rowptr[n + 1];
    float adh = ad[(size_t)n * 4 + hh];
    float nih = ninv[(size_t)n * 4 + hh];
    float acc0 = 0.f, acc1 = 0.f;
    for (int i = beg; i < end; i++) {
        int s = csrsrc[i];                               // warp-uniform broadcast
        float asv = as[(size_t)s * 4 + hh];              // warp-uniform broadcast
        float t = asv + adh; t = t > 0.f ? t : NEG_SLOPE * t;
        float w = __expf(t) * nih;
        float2 v = *reinterpret_cast<const float2*>(h + ((size_t)s * 4 + hh) * C1 + lane * 2);
        acc0 += w * v.x;
        acc1 += w * v.y;
    }
    int c = hh * C1 + lane * 2;
    float o0 = acc0 + bias[c];
    float o1 = acc1 + bias[c + 1];
    float2 o = make_float2(o0 > 0.f ? o0 : 0.f, o1 > 0.f ? o1 : 0.f);
    *reinterpret_cast<float2*>(out + (size_t)n * F1 + c) = o;
}

// ---------------- pull aggregation layer 2 (warp per dst node) -------------
// F2=64 total: each lane owns 2 channels; head = lane/8 (C2=16).
__global__ void agg2_kernel(const int* __restrict__ rowptr, const int* __restrict__ csrsrc,
                            const float* __restrict__ as, const float* __restrict__ ad,
                            const float* __restrict__ ninv, const float* __restrict__ h,
                            const float* __restrict__ bias, float* __restrict__ out, int N) {
    int gw = (blockIdx.x * blockDim.x + threadIdx.x) >> 5;
    int lane = threadIdx.x & 31;
    if (gw >= N) return;
    int hh = lane >> 3;   // (lane*2)/16
    int beg = rowptr[gw], end = rowptr[gw + 1];
    float adh = ad[(size_t)gw * 4 + hh];
    float nih = ninv[(size_t)gw * 4 + hh];
    float acc0 = 0.f, acc1 = 0.f;
    for (int i = beg; i < end; i++) {
        int s = csrsrc[i];
        float asv = as[(size_t)s * 4 + hh];
        float t = asv + adh; t = t > 0.f ? t : NEG_SLOPE * t;
        float w = __expf(t) * nih;
        float2 v = *reinterpret_cast<const float2*>(h + (size_t)s * F2 + lane * 2);
        acc0 += w * v.x;
        acc1 += w * v.y;
    }
    int c = lane * 2;
    float o0 = acc0 + bias[c];
    float o1 = acc1 + bias[c + 1];
    float2 o = make_float2(o0 > 0.f ? o0 : 0.f, o1 > 0.f ? o1 : 0.f);
    *reinterpret_cast<float2*>(out + (size_t)gw * F2 + c) = o;
}

// ---------------- pooling (batch sorted -> run-length accumulation) --------
__global__ void pool_kernel(const float* __restrict__ g, const int* __restrict__ batch,
                            float* __restrict__ pool, int N) {
    int c = blockIdx.y;
    int t = blockIdx.x * blockDim.x + threadIdx.x;
    const int CH = 64;
    int n0 = t * CH;
    if (n0 >= N) return;
    int n1 = min(N, n0 + CH);
    int cur = batch[n0];
    float acc = 0.f;
    for (int n = n0; n < n1; n++) {
        int bb = batch[n];
        if (bb != cur) { atomicAdd(&pool[cur * F2 + c], acc); cur = bb; acc = 0.f; }
        acc += g[(size_t)n * F2 + c];
    }
    atomicAdd(&pool[cur * F2 + c], acc);
}

__global__ void count_kernel(const int* __restrict__ batch, float* __restrict__ cnt, int N) {
    int t = blockIdx.x * blockDim.x + threadIdx.x;
    const int CH = 64;
    int n0 = t * CH;
    if (n0 >= N) return;
    int n1 = min(N, n0 + CH);
    int cur = batch[n0];
    float acc = 0.f;
    for (int n = n0; n < n1; n++) {
        int bb = batch[n];
        if (bb != cur) { atomicAdd(&cnt[cur], acc); cur = bb; acc = 0.f; }
        acc += 1.f;
    }
    atomicAdd(&cnt[cur], acc);
}

// ---------------- final FC --------------------------------------------------
__global__ void fc_kernel(const float* __restrict__ pool, const float* __restrict__ cnt,
                          const float* __restrict__ w, const float* __restrict__ b,
                          float* __restrict__ out) {
    int g = blockIdx.x;
    int j = threadIdx.x;
    float inv = 1.f / fmaxf(cnt[g], 1.f);
    float acc = b[j];
#pragma unroll
    for (int c = 0; c < F2; c++)
        acc += pool[g * F2 + c] * inv * w[c * NOUT + j];
    out[g * NOUT + j] = acc;
}

// ---------------- launch ----------------------------------------------------
extern "C" void kernel_launch(void* const* d_in, const int* in_sizes, int n_in,
                              void* d_out, int out_size) {
    const float* x      = (const float*)d_in[0];
    const int*   ei     = (const int*)  d_in[1];
    const int*   batch  = (const int*)  d_in[2];
    const float* W1     = (const float*)d_in[3];
    const float* a_src1 = (const float*)d_in[4];
    const float* a_dst1 = (const float*)d_in[5];
    const float* b1     = (const float*)d_in[6];
    const float* W2     = (const float*)d_in[7];
    const float* a_src2 = (const float*)d_in[8];
    const float* a_dst2 = (const float*)d_in[9];
    const float* b2     = (const float*)d_in[10];
    const float* fcw    = (const float*)d_in[11];
    const float* fcb    = (const float*)d_in[12];

    int N = in_sizes[0] / F0;     // 50000
    int E = in_sizes[1] / 2;      // 800000
    int ET = E + N;

    float *p_h1, *p_g1, *p_h2, *p_g2, *p_as, *p_ad, *p_ni, *p_pool, *p_cnt;
    int *p_deg, *p_rowptr, *p_rowpos, *p_csrsrc;
    cudaGetSymbolAddress((void**)&p_h1, d_h1);
    cudaGetSymbolAddress((void**)&p_g1, d_g1);
    cudaGetSymbolAddress((void**)&p_h2, d_h2);
    cudaGetSymbolAddress((void**)&p_g2, d_g2);
    cudaGetSymbolAddress((void**)&p_as, d_as);
    cudaGetSymbolAddress((void**)&p_ad, d_ad);
    cudaGetSymbolAddress((void**)&p_ni, d_ni);
    cudaGetSymbolAddress((void**)&p_deg, d_deg);
    cudaGetSymbolAddress((void**)&p_rowptr, d_rowptr);
    cudaGetSymbolAddress((void**)&p_rowpos, d_rowpos);
    cudaGetSymbolAddress((void**)&p_csrsrc, d_csrsrc);
    cudaGetSymbolAddress((void**)&p_pool, d_pool);
    cudaGetSymbolAddress((void**)&p_cnt, d_cnt);

    float* out = (float*)d_out;

    // ---------------- CSR build (shared by both layers) ----------------
    cudaMemsetAsync(p_deg, 0, (size_t)N * sizeof(int));
    hist_kernel<<<(ET + 255) / 256, 256>>>(ei, p_deg, E, N);
    scan_kernel<<<1, 1024>>>(p_deg, p_rowptr, p_rowpos, N);
    scatter_kernel<<<(ET + 255) / 256, 256>>>(ei, p_rowpos, p_csrsrc, E, N);

    // ---------------- layer 1 ----------------
    {
        dim3 grid((N + 63) / 64, F1 / 64);
        sgemm64<<<grid, 256>>>(x, W1, p_h1, N, F1, F0);
    }
    alpha_kernel<C1><<<(N * NHEAD + 255) / 256, 256>>>(p_h1, a_src1, a_dst1, p_as, p_ad, N);
    denom_kernel<<<(N * 32 + 255) / 256, 256>>>(p_rowptr, p_csrsrc, p_as, p_ad, p_ni, N);
    agg1_kernel<<<(N * NHEAD * 32 + 255) / 256, 256>>>(p_rowptr, p_csrsrc, p_as, p_ad,
                                                       p_ni, p_h1, b1, p_g1, N);

    // ---------------- layer 2 ----------------
    {
        dim3 grid((N + 63) / 64, F2 / 64);
        sgemm64<<<grid, 256>>>(p_g1, W2, p_h2, N, F2, F1);
    }
    alpha_kernel<C2><<<(N * NHEAD + 255) / 256, 256>>>(p_h2, a_src2, a_dst2, p_as, p_ad, N);
    denom_kernel<<<(N * 32 + 255) / 256, 256>>>(p_rowptr, p_csrsrc, p_as, p_ad, p_ni, N);
    agg2_kernel<<<(N * 32 + 255) / 256, 256>>>(p_rowptr, p_csrsrc, p_as, p_ad,
                                               p_ni, p_h2, b2, p_g2, N);

    // ---------------- pooling + FC ----------------
    cudaMemsetAsync(p_pool, 0, (size_t)NG * F2 * sizeof(float));
    cudaMemsetAsync(p_cnt, 0, (size_t)NG * sizeof(float));
    {
        int nthreads = (N + 63) / 64;
        dim3 grid((nthreads + 127) / 128, F2);
        pool_kernel<<<grid, 128>>>(p_g2, batch, p_pool, N);
        count_kernel<<<(nthreads + 127) / 128, 128>>>(batch, p_cnt, N);
    }
    fc_kernel<<<NG, NOUT>>>(p_pool, p_cnt, fcw, fcb, out);
}

// round 6
// speedup vs baseline: 1.5169x; 1.2568x over previous
#include <cuda_runtime.h>
#include <cstdint>

// ---------------- problem constants (fixed by setup_inputs) ----------------
#define NN   50000
#define EE   800000
#define ET_MAX (EE+NN)
#define F0   128
#define NHEAD 4
#define C1   64
#define F1   (NHEAD*C1)   // 256
#define C2   16
#define F2   (NHEAD*C2)   // 64
#define NG   64
#define NOUT 32
#define NEG_SLOPE 0.2f

// ---------------- scratch (device globals; no allocation allowed) ----------
__device__ float d_h1[NN*F1];
__device__ float d_g1[NN*F1];
__device__ float d_h2[NN*F2];
__device__ float d_g2[NN*F2];
__device__ float d_as[NN*NHEAD];
__device__ float d_ad[NN*NHEAD];
__device__ int   d_deg[NN];
__device__ int   d_rowptr[NN+1];
__device__ int   d_rowpos[NN];
__device__ int   d_csrsrc[ET_MAX];
__device__ float d_pool[NG*F2];
__device__ float d_cnt[NG];

// ---------------- tf32 helpers ---------------------------------------------
__device__ __forceinline__ float cvt_tf32(float x) {
    uint32_t u;
    asm("cvt.rna.tf32.f32 %0, %1;" : "=r"(u) : "f"(x));
    return __uint_as_float(u);
}

__device__ __forceinline__ void mma_tf32(float* d, const float* a, const float* b) {
    asm volatile(
        "mma.sync.aligned.m16n8k8.row.col.f32.tf32.tf32.f32 "
        "{%0,%1,%2,%3}, {%4,%5,%6,%7}, {%8,%9}, {%0,%1,%2,%3};"
        : "+f"(d[0]), "+f"(d[1]), "+f"(d[2]), "+f"(d[3])
        : "r"(__float_as_uint(a[0])), "r"(__float_as_uint(a[1])),
          "r"(__float_as_uint(a[2])), "r"(__float_as_uint(a[3])),
          "r"(__float_as_uint(b[0])), "r"(__float_as_uint(b[1])));
}

// ---------------- tf32 tensor-core GEMM: C[M,N] = A[M,K] @ B[K,N] ----------
// BM=128, BN=64, BK=16; 256 threads = 8 warps in 4(M) x 2(N); warp tile 32x32.
// Requires K % 16 == 0, N % 64 == 0.
__global__ __launch_bounds__(256) void gemm_tf32(
    const float* __restrict__ A, const float* __restrict__ B,
    float* __restrict__ C, int M, int N, int K)
{
    __shared__ float As[128][20];   // [m][k], pad->20 (conflict-free frag loads)
    __shared__ float Bs[16][68];    // [k][n], pad->68

    int tid  = threadIdx.x;
    int warp = tid >> 5, lane = tid & 31;
    int wm = (warp & 3) * 32;       // warp M offset in block
    int wn = (warp >> 2) * 32;      // warp N offset in block
    int m0 = blockIdx.x * 128;
    int n0 = blockIdx.y * 64;

    int r  = lane >> 2;             // groupID 0..7
    int cg = lane & 3;              // threadID-in-group 0..3

    float acc[2][4][4];
#pragma unroll
    for (int i = 0; i < 2; i++)
#pragma unroll
        for (int j = 0; j < 4; j++)
#pragma unroll
            for (int q = 0; q < 4; q++) acc[i][j][q] = 0.f;

    for (int k0 = 0; k0 < K; k0 += 16) {
        // load A tile 128x16 (2 float4 per thread), store transposed-ish [m][k]
#pragma unroll
        for (int i = 0; i < 2; i++) {
            int t2 = tid + i * 256;
            int m  = t2 >> 2;
            int kq = (t2 & 3) * 4;
            int gm = m0 + m; if (gm > M - 1) gm = M - 1;
            float4 v = *reinterpret_cast<const float4*>(&A[(size_t)gm * K + k0 + kq]);
            As[m][kq + 0] = cvt_tf32(v.x);
            As[m][kq + 1] = cvt_tf32(v.y);
            As[m][kq + 2] = cvt_tf32(v.z);
            As[m][kq + 3] = cvt_tf32(v.w);
        }
        // load B tile 16x64 (1 float4 per thread)
        {
            int k  = tid >> 4;
            int nq = (tid & 15) * 4;
            float4 v = *reinterpret_cast<const float4*>(&B[(size_t)(k0 + k) * N + n0 + nq]);
            Bs[k][nq + 0] = cvt_tf32(v.x);
            Bs[k][nq + 1] = cvt_tf32(v.y);
            Bs[k][nq + 2] = cvt_tf32(v.z);
            Bs[k][nq + 3] = cvt_tf32(v.w);
        }
        __syncthreads();

#pragma unroll
        for (int ks = 0; ks < 16; ks += 8) {
            float a[2][4];
#pragma unroll
            for (int mt = 0; mt < 2; mt++) {
                int mrow = wm + mt * 16 + r;
                a[mt][0] = As[mrow    ][ks + cg    ];
                a[mt][1] = As[mrow + 8][ks + cg    ];
                a[mt][2] = As[mrow    ][ks + cg + 4];
                a[mt][3] = As[mrow + 8][ks + cg + 4];
            }
            float b[4][2];
#pragma unroll
            for (int nt = 0; nt < 4; nt++) {
                b[nt][0] = Bs[ks + cg    ][wn + nt * 8 + r];
                b[nt][1] = Bs[ks + cg + 4][wn + nt * 8 + r];
            }
#pragma unroll
            for (int mt = 0; mt < 2; mt++)
#pragma unroll
                for (int nt = 0; nt < 4; nt++)
                    mma_tf32(acc[mt][nt], a[mt], b[nt]);
        }
        __syncthreads();
    }

#pragma unroll
    for (int mt = 0; mt < 2; mt++) {
#pragma unroll
        for (int nt = 0; nt < 4; nt++) {
            int row = m0 + wm + mt * 16 + r;
            int col = n0 + wn + nt * 8 + 2 * cg;
            if (row < M) {
                float2 o = make_float2(acc[mt][nt][0], acc[mt][nt][1]);
                *reinterpret_cast<float2*>(&C[(size_t)row * N + col]) = o;
            }
            if (row + 8 < M) {
                float2 o = make_float2(acc[mt][nt][2], acc[mt][nt][3]);
                *reinterpret_cast<float2*>(&C[(size_t)(row + 8) * N + col]) = o;
            }
        }
    }
}

// ---------------- CSR build: histogram -> scan -> scatter -------------------
__global__ void hist_kernel(const int* __restrict__ ei, int* __restrict__ deg,
                            int E, int N) {
    int e = blockIdx.x * blockDim.x + threadIdx.x;
    if (e >= E + N) return;
    int d = (e < E) ? ei[E + e] : (e - E);
    atomicAdd(&deg[d], 1);
}

__global__ void scan_kernel(const int* __restrict__ deg, int* __restrict__ rowptr,
                            int* __restrict__ rowpos, int N) {
    __shared__ int sums[1024];
    int t = threadIdx.x;
    int CH = (N + 1023) / 1024;
    int b = t * CH, e = min(N, b + CH);
    int s = 0;
    for (int i = b; i < e; i++) s += deg[i];
    sums[t] = s;
    __syncthreads();
    for (int off = 1; off < 1024; off <<= 1) {
        int v = (t >= off) ? sums[t - off] : 0;
        __syncthreads();
        sums[t] += v;
        __syncthreads();
    }
    int run = (t == 0) ? 0 : sums[t - 1];
    for (int i = b; i < e; i++) {
        rowptr[i] = run;
        rowpos[i] = run;
        run += deg[i];
    }
    if (t == 1023) rowptr[N] = sums[1023];
}

__global__ void scatter_kernel(const int* __restrict__ ei, int* __restrict__ rowpos,
                               int* __restrict__ csrsrc, int E, int N) {
    int e = blockIdx.x * blockDim.x + threadIdx.x;
    if (e >= E + N) return;
    int s, d;
    if (e < E) { s = ei[e]; d = ei[E + e]; } else { s = d = e - E; }
    int pos = atomicAdd(&rowpos[d], 1);
    csrsrc[pos] = s;
}

// ---------------- per-node attention logits --------------------------------
template<int C>
__global__ void alpha_kernel(const float* __restrict__ h,
                             const float* __restrict__ asr, const float* __restrict__ adt,
                             float* __restrict__ outs, float* __restrict__ outd, int N) {
    int idx = blockIdx.x * blockDim.x + threadIdx.x;
    if (idx >= N * NHEAD) return;
    int hh = idx & (NHEAD - 1);
    const float* hp = h + (size_t)idx * C;
    const float* ap = asr + hh * C;
    const float* dp = adt + hh * C;
    float ss = 0.f, dd = 0.f;
#pragma unroll
    for (int i = 0; i < C; i += 4) {
        float4 v = *reinterpret_cast<const float4*>(hp + i);
        float4 a = *reinterpret_cast<const float4*>(ap + i);
        float4 d = *reinterpret_cast<const float4*>(dp + i);
        ss += v.x * a.x + v.y * a.y + v.z * a.z + v.w * a.w;
        dd += v.x * d.x + v.y * d.y + v.z * d.z + v.w * d.w;
    }
    outs[idx] = ss;
    outd[idx] = dd;
}

// ---------------- pull aggregation layer 1 (warp per (dst, head)) ----------
// Fused softmax denominator + bias + relu. C1=64: each lane owns 2 channels.
__global__ void agg1_kernel(const int* __restrict__ rowptr, const int* __restrict__ csrsrc,
                            const float* __restrict__ as, const float* __restrict__ ad,
                            const float* __restrict__ h,
                            const float* __restrict__ bias, float* __restrict__ out, int N) {
    int gw = (blockIdx.x * blockDim.x + threadIdx.x) >> 5;
    int lane = threadIdx.x & 31;
    if (gw >= N * NHEAD) return;
    int n = gw >> 2, hh = gw & 3;
    int beg = rowptr[n], end = rowptr[n + 1];
    float adh = ad[(size_t)n * 4 + hh];
    float acc0 = 0.f, acc1 = 0.f, wsum = 0.f;
    for (int i = beg; i < end; i++) {
        int s = csrsrc[i];                      // warp-uniform broadcast
        float asv = as[(size_t)s * 4 + hh];     // warp-uniform broadcast
        float t = asv + adh; t = t > 0.f ? t : NEG_SLOPE * t;
        float w = __expf(t);
        wsum += w;
        float2 v = *reinterpret_cast<const float2*>(h + ((size_t)s * 4 + hh) * C1 + lane * 2);
        acc0 += w * v.x;
        acc1 += w * v.y;
    }
    float inv = 1.f / wsum;
    int c = hh * C1 + lane * 2;
    float o0 = acc0 * inv + bias[c];
    float o1 = acc1 * inv + bias[c + 1];
    float2 o = make_float2(o0 > 0.f ? o0 : 0.f, o1 > 0.f ? o1 : 0.f);
    *reinterpret_cast<float2*>(out + (size_t)n * F1 + c) = o;
}

// ---------------- pull aggregation layer 2 (warp per dst node) -------------
// F2=64 total: each lane owns 2 channels; head = lane/8 (C2=16).
__global__ void agg2_kernel(const int* __restrict__ rowptr, const int* __restrict__ csrsrc,
                            const float* __restrict__ as, const float* __restrict__ ad,
                            const float* __restrict__ h,
                            const float* __restrict__ bias, float* __restrict__ out, int N) {
    int gw = (blockIdx.x * blockDim.x + threadIdx.x) >> 5;
    int lane = threadIdx.x & 31;
    if (gw >= N) return;
    int hh = lane >> 3;
    int beg = rowptr[gw], end = rowptr[gw + 1];
    float adh = ad[(size_t)gw * 4 + hh];
    float acc0 = 0.f, acc1 = 0.f, wsum = 0.f;
    for (int i = beg; i < end; i++) {
        int s = csrsrc[i];
        float asv = as[(size_t)s * 4 + hh];
        float t = asv + adh; t = t > 0.f ? t : NEG_SLOPE * t;
        float w = __expf(t);
        wsum += w;
        float2 v = *reinterpret_cast<const float2*>(h + (size_t)s * F2 + lane * 2);
        acc0 += w * v.x;
        acc1 += w * v.y;
    }
    float inv = 1.f / wsum;
    int c = lane * 2;
    float o0 = acc0 * inv + bias[c];
    float o1 = acc1 * inv + bias[c + 1];
    float2 o = make_float2(o0 > 0.f ? o0 : 0.f, o1 > 0.f ? o1 : 0.f);
    *reinterpret_cast<float2*>(out + (size_t)gw * F2 + c) = o;
}

// ---------------- pooling (batch sorted -> run-length accumulation) --------
__global__ void pool_kernel(const float* __restrict__ g, const int* __restrict__ batch,
                            float* __restrict__ pool, int N) {
    int c = blockIdx.y;
    int t = blockIdx.x * blockDim.x + threadIdx.x;
    const int CH = 64;
    int n0 = t * CH;
    if (n0 >= N) return;
    int n1 = min(N, n0 + CH);
    int cur = batch[n0];
    float acc = 0.f;
    for (int n = n0; n < n1; n++) {
        int bb = batch[n];
        if (bb != cur) { atomicAdd(&pool[cur * F2 + c], acc); cur = bb; acc = 0.f; }
        acc += g[(size_t)n * F2 + c];
    }
    atomicAdd(&pool[cur * F2 + c], acc);
}

__global__ void count_kernel(const int* __restrict__ batch, float* __restrict__ cnt, int N) {
    int t = blockIdx.x * blockDim.x + threadIdx.x;
    const int CH = 64;
    int n0 = t * CH;
    if (n0 >= N) return;
    int n1 = min(N, n0 + CH);
    int cur = batch[n0];
    float acc = 0.f;
    for (int n = n0; n < n1; n++) {
        int bb = batch[n];
        if (bb != cur) { atomicAdd(&cnt[cur], acc); cur = bb; acc = 0.f; }
        acc += 1.f;
    }
    atomicAdd(&cnt[cur], acc);
}

// ---------------- final FC --------------------------------------------------
__global__ void fc_kernel(const float* __restrict__ pool, const float* __restrict__ cnt,
                          const float* __restrict__ w, const float* __restrict__ b,
                          float* __restrict__ out) {
    int g = blockIdx.x;
    int j = threadIdx.x;
    float inv = 1.f / fmaxf(cnt[g], 1.f);
    float acc = b[j];
#pragma unroll
    for (int c = 0; c < F2; c++)
        acc += pool[g * F2 + c] * inv * w[c * NOUT + j];
    out[g * NOUT + j] = acc;
}

// ---------------- launch ----------------------------------------------------
extern "C" void kernel_launch(void* const* d_in, const int* in_sizes, int n_in,
                              void* d_out, int out_size) {
    const float* x      = (const float*)d_in[0];
    const int*   ei     = (const int*)  d_in[1];
    const int*   batch  = (const int*)  d_in[2];
    const float* W1     = (const float*)d_in[3];
    const float* a_src1 = (const float*)d_in[4];
    const float* a_dst1 = (const float*)d_in[5];
    const float* b1     = (const float*)d_in[6];
    const float* W2     = (const float*)d_in[7];
    const float* a_src2 = (const float*)d_in[8];
    const float* a_dst2 = (const float*)d_in[9];
    const float* b2     = (const float*)d_in[10];
    const float* fcw    = (const float*)d_in[11];
    const float* fcb    = (const float*)d_in[12];

    int N = in_sizes[0] / F0;     // 50000
    int E = in_sizes[1] / 2;      // 800000
    int ET = E + N;

    float *p_h1, *p_g1, *p_h2, *p_g2, *p_as, *p_ad, *p_pool, *p_cnt;
    int *p_deg, *p_rowptr, *p_rowpos, *p_csrsrc;
    cudaGetSymbolAddress((void**)&p_h1, d_h1);
    cudaGetSymbolAddress((void**)&p_g1, d_g1);
    cudaGetSymbolAddress((void**)&p_h2, d_h2);
    cudaGetSymbolAddress((void**)&p_g2, d_g2);
    cudaGetSymbolAddress((void**)&p_as, d_as);
    cudaGetSymbolAddress((void**)&p_ad, d_ad);
    cudaGetSymbolAddress((void**)&p_deg, d_deg);
    cudaGetSymbolAddress((void**)&p_rowptr, d_rowptr);
    cudaGetSymbolAddress((void**)&p_rowpos, d_rowpos);
    cudaGetSymbolAddress((void**)&p_csrsrc, d_csrsrc);
    cudaGetSymbolAddress((void**)&p_pool, d_pool);
    cudaGetSymbolAddress((void**)&p_cnt, d_cnt);

    float* out = (float*)d_out;

    // ---------------- CSR build (shared by both layers) ----------------
    cudaMemsetAsync(p_deg, 0, (size_t)N * sizeof(int));
    hist_kernel<<<(ET + 255) / 256, 256>>>(ei, p_deg, E, N);
    scan_kernel<<<1, 1024>>>(p_deg, p_rowptr, p_rowpos, N);
    scatter_kernel<<<(ET + 255) / 256, 256>>>(ei, p_rowpos, p_csrsrc, E, N);

    // ---------------- layer 1 ----------------
    {
        dim3 grid((N + 127) / 128, F1 / 64);
        gemm_tf32<<<grid, 256>>>(x, W1, p_h1, N, F1, F0);
    }
    alpha_kernel<C1><<<(N * NHEAD + 255) / 256, 256>>>(p_h1, a_src1, a_dst1, p_as, p_ad, N);
    agg1_kernel<<<(N * NHEAD * 32 + 255) / 256, 256>>>(p_rowptr, p_csrsrc, p_as, p_ad,
                                                       p_h1, b1, p_g1, N);

    // ---------------- layer 2 ----------------
    {
        dim3 grid((N + 127) / 128, F2 / 64);
        gemm_tf32<<<grid, 256>>>(p_g1, W2, p_h2, N, F2, F1);
    }
    alpha_kernel<C2><<<(N * NHEAD + 255) / 256, 256>>>(p_h2, a_src2, a_dst2, p_as, p_ad, N);
    agg2_kernel<<<(N * 32 + 255) / 256, 256>>>(p_rowptr, p_csrsrc, p_as, p_ad,
                                               p_h2, b2, p_g2, N);

    // ---------------- pooling + FC ----------------
    cudaMemsetAsync(p_pool, 0, (size_t)NG * F2 * sizeof(float));
    cudaMemsetAsync(p_cnt, 0, (size_t)NG * sizeof(float));
    {
        int nthreads = (N + 63) / 64;
        dim3 grid((nthreads + 127) / 128, F2);
        pool_kernel<<<grid, 128>>>(p_g2, batch, p_pool, N);
        count_kernel<<<(nthreads + 127) / 128, 128>>>(batch, p_cnt, N);
    }
    fc_kernel<<<NG, NOUT>>>(p_pool, p_cnt, fcw, fcb, out);
}

// round 9
// speedup vs baseline: 1.7630x; 1.1622x over previous
#include <cuda_runtime.h>
#include <cstdint>

// ---------------- problem constants (fixed by setup_inputs) ----------------
#define NN   50000
#define EE   800000
#define ET_MAX (EE+NN)
#define F0   128
#define NHEAD 4
#define C1   64
#define F1   (NHEAD*C1)   // 256
#define C2   16
#define F2   (NHEAD*C2)   // 64
#define NG   64
#define NOUT 32
#define NEG_SLOPE 0.2f

// ---------------- scratch (device globals; no allocation allowed) ----------
__device__ float d_h1[NN*F1];
__device__ float d_g1[NN*F1];
__device__ float d_h2[NN*F2];
__device__ float d_g2[NN*F2];
__device__ float d_as[NN*NHEAD];
__device__ float d_ad[NN*NHEAD];
__device__ int   d_deg[NN];
__device__ int   d_rowptr[NN+1];
__device__ int   d_rowpos[NN];
__device__ int   d_csrsrc[ET_MAX];
__device__ float d_pool[NG*F2];
__device__ float d_cnt[NG];

// ---------------- async copy helpers ---------------------------------------
__device__ __forceinline__ void cp_async16(void* smem, const void* gmem) {
    uint32_t s = (uint32_t)__cvta_generic_to_shared(smem);
    asm volatile("cp.async.ca.shared.global [%0], [%1], 16;" :: "r"(s), "l"(gmem));
}
__device__ __forceinline__ void cp_commit() {
    asm volatile("cp.async.commit_group;");
}
__device__ __forceinline__ void cp_wait0() {
    asm volatile("cp.async.wait_group 0;");
}

// round-to-nearest tf32 conversion (UNBIASED — truncation accumulates bias
// linearly over K and blew past the 1e-3 gate in round 8)
__device__ __forceinline__ uint32_t cvt_tf32(float x) {
    uint32_t u;
    asm("cvt.rna.tf32.f32 %0, %1;" : "=r"(u) : "f"(x));
    return u;
}

__device__ __forceinline__ void mma_tf32(float* d, const uint32_t* a, const uint32_t* b) {
    asm volatile(
        "mma.sync.aligned.m16n8k8.row.col.f32.tf32.tf32.f32 "
        "{%0,%1,%2,%3}, {%4,%5,%6,%7}, {%8,%9}, {%0,%1,%2,%3};"
        : "+f"(d[0]), "+f"(d[1]), "+f"(d[2]), "+f"(d[3])
        : "r"(a[0]), "r"(a[1]), "r"(a[2]), "r"(a[3]),
          "r"(b[0]), "r"(b[1]));
}

// ---------------- tf32 tensor-core GEMM, cp.async double-buffered ----------
// BM=128, BN=64, BK=16; 256 threads = 8 warps in 4(M) x 2(N); warp tile 32x32.
// fp32 loaded raw via cp.async; .rna conversion applied to register fragments.
// Requires K % 16 == 0, N % 64 == 0.
__global__ __launch_bounds__(256) void gemm_tf32(
    const float* __restrict__ A, const float* __restrict__ B,
    float* __restrict__ C, int M, int N, int K)
{
    __shared__ float As[2][128][20];   // [m][k], pad 20 floats
    __shared__ float Bs[2][16][72];    // [k][n], pad 72 floats

    int tid  = threadIdx.x;
    int warp = tid >> 5, lane = tid & 31;
    int wm = (warp & 3) * 32;
    int wn = (warp >> 2) * 32;
    int m0 = blockIdx.x * 128;
    int n0 = blockIdx.y * 64;

    int r  = lane >> 2;
    int cg = lane & 3;

    int am0 = tid >> 2;
    int akq = (tid & 3) * 4;
    int bk  = tid >> 4;
    int bnq = (tid & 15) * 4;

    float acc[2][4][4];
#pragma unroll
    for (int i = 0; i < 2; i++)
#pragma unroll
        for (int j = 0; j < 4; j++)
#pragma unroll
            for (int q = 0; q < 4; q++) acc[i][j][q] = 0.f;

    int nk = K >> 4;

    // ---- prologue: load tile 0 into buffer 0 ----
    {
        int gm0 = m0 + am0;       if (gm0 > M - 1) gm0 = M - 1;
        int gm1 = m0 + am0 + 64;  if (gm1 > M - 1) gm1 = M - 1;
        cp_async16(&As[0][am0     ][akq], &A[(size_t)gm0 * K + akq]);
        cp_async16(&As[0][am0 + 64][akq], &A[(size_t)gm1 * K + akq]);
        cp_async16(&Bs[0][bk][bnq], &B[(size_t)bk * N + n0 + bnq]);
        cp_commit();
    }

    for (int t = 0; t < nk; t++) {
        cp_wait0();
        __syncthreads();
        int buf = t & 1;

        // ---- prefetch next tile into other buffer ----
        if (t + 1 < nk) {
            int k0 = (t + 1) << 4;
            int gm0 = m0 + am0;       if (gm0 > M - 1) gm0 = M - 1;
            int gm1 = m0 + am0 + 64;  if (gm1 > M - 1) gm1 = M - 1;
            cp_async16(&As[buf ^ 1][am0     ][akq], &A[(size_t)gm0 * K + k0 + akq]);
            cp_async16(&As[buf ^ 1][am0 + 64][akq], &A[(size_t)gm1 * K + k0 + akq]);
            cp_async16(&Bs[buf ^ 1][bk][bnq], &B[(size_t)(k0 + bk) * N + n0 + bnq]);
            cp_commit();
        }

        // ---- compute on current buffer; cvt.rna on fragments ----
#pragma unroll
        for (int ks = 0; ks < 16; ks += 8) {
            uint32_t a[2][4];
#pragma unroll
            for (int mt = 0; mt < 2; mt++) {
                int mrow = wm + mt * 16 + r;
                a[mt][0] = cvt_tf32(As[buf][mrow    ][ks + cg    ]);
                a[mt][1] = cvt_tf32(As[buf][mrow + 8][ks + cg    ]);
                a[mt][2] = cvt_tf32(As[buf][mrow    ][ks + cg + 4]);
                a[mt][3] = cvt_tf32(As[buf][mrow + 8][ks + cg + 4]);
            }
            uint32_t b[4][2];
#pragma unroll
            for (int nt = 0; nt < 4; nt++) {
                b[nt][0] = cvt_tf32(Bs[buf][ks + cg    ][wn + nt * 8 + r]);
                b[nt][1] = cvt_tf32(Bs[buf][ks + cg + 4][wn + nt * 8 + r]);
            }
#pragma unroll
            for (int mt = 0; mt < 2; mt++)
#pragma unroll
                for (int nt = 0; nt < 4; nt++)
                    mma_tf32(acc[mt][nt], a[mt], b[nt]);
        }
        __syncthreads();
    }

#pragma unroll
    for (int mt = 0; mt < 2; mt++) {
#pragma unroll
        for (int nt = 0; nt < 4; nt++) {
            int row = m0 + wm + mt * 16 + r;
            int col = n0 + wn + nt * 8 + 2 * cg;
            if (row < M) {
                float2 o = make_float2(acc[mt][nt][0], acc[mt][nt][1]);
                *reinterpret_cast<float2*>(&C[(size_t)row * N + col]) = o;
            }
            if (row + 8 < M) {
                float2 o = make_float2(acc[mt][nt][2], acc[mt][nt][3]);
                *reinterpret_cast<float2*>(&C[(size_t)(row + 8) * N + col]) = o;
            }
        }
    }
}

// ---------------- CSR build: histogram -> scan -> scatter -------------------
__global__ void hist_kernel(const int* __restrict__ ei, int* __restrict__ deg,
                            int E, int N) {
    int e = blockIdx.x * blockDim.x + threadIdx.x;
    if (e >= E + N) return;
    int d = (e < E) ? ei[E + e] : (e - E);
    atomicAdd(&deg[d], 1);
}

__global__ void scan_kernel(const int* __restrict__ deg, int* __restrict__ rowptr,
                            int* __restrict__ rowpos, int N) {
    __shared__ int sums[1024];
    int t = threadIdx.x;
    int CH = (N + 1023) / 1024;
    int b = t * CH, e = min(N, b + CH);
    int s = 0;
    for (int i = b; i < e; i++) s += deg[i];
    sums[t] = s;
    __syncthreads();
    for (int off = 1; off < 1024; off <<= 1) {
        int v = (t >= off) ? sums[t - off] : 0;
        __syncthreads();
        sums[t] += v;
        __syncthreads();
    }
    int run = (t == 0) ? 0 : sums[t - 1];
    for (int i = b; i < e; i++) {
        rowptr[i] = run;
        rowpos[i] = run;
        run += deg[i];
    }
    if (t == 1023) rowptr[N] = sums[1023];
}

__global__ void scatter_kernel(const int* __restrict__ ei, int* __restrict__ rowpos,
                               int* __restrict__ csrsrc, int E, int N) {
    int e = blockIdx.x * blockDim.x + threadIdx.x;
    if (e >= E + N) return;
    int s, d;
    if (e < E) { s = ei[e]; d = ei[E + e]; } else { s = d = e - E; }
    int pos = atomicAdd(&rowpos[d], 1);
    csrsrc[pos] = s;
}

// ---------------- per-node attention logits --------------------------------
template<int C>
__global__ void alpha_kernel(const float* __restrict__ h,
                             const float* __restrict__ asr, const float* __restrict__ adt,
                             float* __restrict__ outs, float* __restrict__ outd, int N) {
    int idx = blockIdx.x * blockDim.x + threadIdx.x;
    if (idx >= N * NHEAD) return;
    int hh = idx & (NHEAD - 1);
    const float* hp = h + (size_t)idx * C;
    const float* ap = asr + hh * C;
    const float* dp = adt + hh * C;
    float ss = 0.f, dd = 0.f;
#pragma unroll
    for (int i = 0; i < C; i += 4) {
        float4 v = *reinterpret_cast<const float4*>(hp + i);
        float4 a = *reinterpret_cast<const float4*>(ap + i);
        float4 d = *reinterpret_cast<const float4*>(dp + i);
        ss += v.x * a.x + v.y * a.y + v.z * a.z + v.w * a.w;
        dd += v.x * d.x + v.y * d.y + v.z * d.z + v.w * d.w;
    }
    outs[idx] = ss;
    outd[idx] = dd;
}

// ---------------- pull aggregation layer 1 (warp per dst, all heads) -------
// Lane owns 8 contiguous channels of the 256-wide row; head = lane>>3.
// Fused softmax denominator + bias + relu.
__global__ void agg1_kernel(const int* __restrict__ rowptr, const int* __restrict__ csrsrc,
                            const float* __restrict__ as, const float* __restrict__ ad,
                            const float* __restrict__ h,
                            const float* __restrict__ bias, float* __restrict__ out, int N) {
    int gw = (blockIdx.x * blockDim.x + threadIdx.x) >> 5;
    int lane = threadIdx.x & 31;
    if (gw >= N) return;
    int hh = lane >> 3;
    int beg = rowptr[gw], end = rowptr[gw + 1];
    float adh = ad[(size_t)gw * 4 + hh];
    float4 acc0 = make_float4(0.f, 0.f, 0.f, 0.f);
    float4 acc1 = make_float4(0.f, 0.f, 0.f, 0.f);
    float wsum = 0.f;
    for (int i = beg; i < end; i++) {
        int s = csrsrc[i];                      // warp-uniform broadcast
        float asv = as[(size_t)s * 4 + hh];     // 4 distinct addrs per warp
        float t = asv + adh; t = t > 0.f ? t : NEG_SLOPE * t;
        float w = __expf(t);
        wsum += w;
        const float4* hp = reinterpret_cast<const float4*>(h + (size_t)s * F1 + lane * 8);
        float4 v0 = hp[0], v1 = hp[1];
        acc0.x += w * v0.x; acc0.y += w * v0.y; acc0.z += w * v0.z; acc0.w += w * v0.w;
        acc1.x += w * v1.x; acc1.y += w * v1.y; acc1.z += w * v1.z; acc1.w += w * v1.w;
    }
    float inv = 1.f / wsum;
    int c = lane * 8;
    const float4* bp = reinterpret_cast<const float4*>(bias + c);
    float4 b0 = bp[0], b1 = bp[1];
    float4 o0, o1;
    o0.x = fmaxf(acc0.x * inv + b0.x, 0.f); o0.y = fmaxf(acc0.y * inv + b0.y, 0.f);
    o0.z = fmaxf(acc0.z * inv + b0.z, 0.f); o0.w = fmaxf(acc0.w * inv + b0.w, 0.f);
    o1.x = fmaxf(acc1.x * inv + b1.x, 0.f); o1.y = fmaxf(acc1.y * inv + b1.y, 0.f);
    o1.z = fmaxf(acc1.z * inv + b1.z, 0.f); o1.w = fmaxf(acc1.w * inv + b1.w, 0.f);
    float4* op = reinterpret_cast<float4*>(out + (size_t)gw * F1 + c);
    op[0] = o0; op[1] = o1;
}

// ---------------- pull aggregation layer 2 (warp per dst node) -------------
// F2=64 total: each lane owns 2 channels; head = lane/8 (C2=16).
__global__ void agg2_kernel(const int* __restrict__ rowptr, const int* __restrict__ csrsrc,
                            const float* __restrict__ as, const float* __restrict__ ad,
                            const float* __restrict__ h,
                            const float* __restrict__ bias, float* __restrict__ out, int N) {
    int gw = (blockIdx.x * blockDim.x + threadIdx.x) >> 5;
    int lane = threadIdx.x & 31;
    if (gw >= N) return;
    int hh = lane >> 3;
    int beg = rowptr[gw], end = rowptr[gw + 1];
    float adh = ad[(size_t)gw * 4 + hh];
    float acc0 = 0.f, acc1 = 0.f, wsum = 0.f;
    for (int i = beg; i < end; i++) {
        int s = csrsrc[i];
        float asv = as[(size_t)s * 4 + hh];
        float t = asv + adh; t = t > 0.f ? t : NEG_SLOPE * t;
        float w = __expf(t);
        wsum += w;
        float2 v = *reinterpret_cast<const float2*>(h + (size_t)s * F2 + lane * 2);
        acc0 += w * v.x;
        acc1 += w * v.y;
    }
    float inv = 1.f / wsum;
    int c = lane * 2;
    float o0 = acc0 * inv + bias[c];
    float o1 = acc1 * inv + bias[c + 1];
    float2 o = make_float2(o0 > 0.f ? o0 : 0.f, o1 > 0.f ? o1 : 0.f);
    *reinterpret_cast<float2*>(out + (size_t)gw * F2 + c) = o;
}

// ---------------- pooling (batch sorted -> run-length accumulation) --------
__global__ void pool_kernel(const float* __restrict__ g, const int* __restrict__ batch,
                            float* __restrict__ pool, int N) {
    int c = blockIdx.y;
    int t = blockIdx.x * blockDim.x + threadIdx.x;
    const int CH = 64;
    int n0 = t * CH;
    if (n0 >= N) return;
    int n1 = min(N, n0 + CH);
    int cur = batch[n0];
    float acc = 0.f;
    for (int n = n0; n < n1; n++) {
        int bb = batch[n];
        if (bb != cur) { atomicAdd(&pool[cur * F2 + c], acc); cur = bb; acc = 0.f; }
        acc += g[(size_t)n * F2 + c];
    }
    atomicAdd(&pool[cur * F2 + c], acc);
}

__global__ void count_kernel(const int* __restrict__ batch, float* __restrict__ cnt, int N) {
    int t = blockIdx.x * blockDim.x + threadIdx.x;
    const int CH = 64;
    int n0 = t * CH;
    if (n0 >= N) return;
    int n1 = min(N, n0 + CH);
    int cur = batch[n0];
    float acc = 0.f;
    for (int n = n0; n < n1; n++) {
        int bb = batch[n];
        if (bb != cur) { atomicAdd(&cnt[cur], acc); cur = bb; acc = 0.f; }
        acc += 1.f;
    }
    atomicAdd(&cnt[cur], acc);
}

// ---------------- final FC --------------------------------------------------
__global__ void fc_kernel(const float* __restrict__ pool, const float* __restrict__ cnt,
                          const float* __restrict__ w, const float* __restrict__ b,
                          float* __restrict__ out) {
    int g = blockIdx.x;
    int j = threadIdx.x;
    float inv = 1.f / fmaxf(cnt[g], 1.f);
    float acc = b[j];
#pragma unroll
    for (int c = 0; c < F2; c++)
        acc += pool[g * F2 + c] * inv * w[c * NOUT + j];
    out[g * NOUT + j] = acc;
}

// ---------------- launch ----------------------------------------------------
extern "C" void kernel_launch(void* const* d_in, const int* in_sizes, int n_in,
                              void* d_out, int out_size) {
    const float* x      = (const float*)d_in[0];
    const int*   ei     = (const int*)  d_in[1];
    const int*   batch  = (const int*)  d_in[2];
    const float* W1     = (const float*)d_in[3];
    const float* a_src1 = (const float*)d_in[4];
    const float* a_dst1 = (const float*)d_in[5];
    const float* b1     = (const float*)d_in[6];
    const float* W2     = (const float*)d_in[7];
    const float* a_src2 = (const float*)d_in[8];
    const float* a_dst2 = (const float*)d_in[9];
    const float* b2     = (const float*)d_in[10];
    const float* fcw    = (const float*)d_in[11];
    const float* fcb    = (const float*)d_in[12];

    int N = in_sizes[0] / F0;     // 50000
    int E = in_sizes[1] / 2;      // 800000
    int ET = E + N;

    float *p_h1, *p_g1, *p_h2, *p_g2, *p_as, *p_ad, *p_pool, *p_cnt;
    int *p_deg, *p_rowptr, *p_rowpos, *p_csrsrc;
    cudaGetSymbolAddress((void**)&p_h1, d_h1);
    cudaGetSymbolAddress((void**)&p_g1, d_g1);
    cudaGetSymbolAddress((void**)&p_h2, d_h2);
    cudaGetSymbolAddress((void**)&p_g2, d_g2);
    cudaGetSymbolAddress((void**)&p_as, d_as);
    cudaGetSymbolAddress((void**)&p_ad, d_ad);
    cudaGetSymbolAddress((void**)&p_deg, d_deg);
    cudaGetSymbolAddress((void**)&p_rowptr, d_rowptr);
    cudaGetSymbolAddress((void**)&p_rowpos, d_rowpos);
    cudaGetSymbolAddress((void**)&p_csrsrc, d_csrsrc);
    cudaGetSymbolAddress((void**)&p_pool, d_pool);
    cudaGetSymbolAddress((void**)&p_cnt, d_cnt);

    float* out = (float*)d_out;

    // ---------------- CSR build (shared by both layers) ----------------
    cudaMemsetAsync(p_deg, 0, (size_t)N * sizeof(int));
    hist_kernel<<<(ET + 255) / 256, 256>>>(ei, p_deg, E, N);
    scan_kernel<<<1, 1024>>>(p_deg, p_rowptr, p_rowpos, N);
    scatter_kernel<<<(ET + 255) / 256, 256>>>(ei, p_rowpos, p_csrsrc, E, N);

    // ---------------- layer 1 ----------------
    {
        dim3 grid((N + 127) / 128, F1 / 64);
        gemm_tf32<<<grid, 256>>>(x, W1, p_h1, N, F1, F0);
    }
    alpha_kernel<C1><<<(N * NHEAD + 255) / 256, 256>>>(p_h1, a_src1, a_dst1, p_as, p_ad, N);
    agg1_kernel<<<(N * 32 + 255) / 256, 256>>>(p_rowptr, p_csrsrc, p_as, p_ad,
                                               p_h1, b1, p_g1, N);

    // ---------------- layer 2 ----------------
    {
        dim3 grid((N + 127) / 128, F2 / 64);
        gemm_tf32<<<grid, 256>>>(p_g1, W2, p_h2, N, F2, F1);
    }
    alpha_kernel<C2><<<(N * NHEAD + 255) / 256, 256>>>(p_h2, a_src2, a_dst2, p_as, p_ad, N);
    agg2_kernel<<<(N * 32 + 255) / 256, 256>>>(p_rowptr, p_csrsrc, p_as, p_ad,
                                               p_h2, b2, p_g2, N);

    // ---------------- pooling + FC ----------------
    cudaMemsetAsync(p_pool, 0, (size_t)NG * F2 * sizeof(float));
    cudaMemsetAsync(p_cnt, 0, (size_t)NG * sizeof(float));
    {
        int nthreads = (N + 63) / 64;
        dim3 grid((nthreads + 127) / 128, F2);
        pool_kernel<<<grid, 128>>>(p_g2, batch, p_pool, N);
        count_kernel<<<(nthreads + 127) / 128, 128>>>(batch, p_cnt, N);
    }
    fc_kernel<<<NG, NOUT>>>(p_pool, p_cnt, fcw, fcb, out);
}

// round 10
// speedup vs baseline: 1.9143x; 1.0858x over previous
#include <cuda_runtime.h>
#include <cuda_fp16.h>
#include <cstdint>

// ---------------- problem constants (fixed by setup_inputs) ----------------
#define NN   50000
#define EE   800000
#define ET_MAX (EE+NN)
#define F0   128
#define NHEAD 4
#define C1   64
#define F1   (NHEAD*C1)   // 256
#define C2   16
#define F2   (NHEAD*C2)   // 64
#define NG   64
#define NOUT 32
#define NEG_SLOPE 0.2f

// ---------------- scratch (device globals; no allocation allowed) ----------
__device__ __half d_h1[NN*F1];         // layer1 features, fp16 (25.6 MB)
__device__ float  d_g1[NN*F1];         // layer1 aggregated (ALSO reused as tf32-rounded x before agg1 writes it)
__device__ __half d_h2[NN*F2];         // layer2 features, fp16
__device__ float  d_g2[NN*F2];
__device__ float  d_w1r[F0*F1];        // tf32-rounded W1
__device__ float  d_w2r[F1*F2];        // tf32-rounded W2
__device__ float  d_as[NN*NHEAD];
__device__ float  d_ad[NN*NHEAD];
__device__ int    d_deg[NN];
__device__ int    d_rowptr[NN+1];
__device__ int    d_rowpos[NN];
__device__ int    d_csrsrc[ET_MAX];
__device__ float  d_pool[NG*F2];
__device__ float  d_cnt[NG];

// ---------------- helpers ---------------------------------------------------
__device__ __forceinline__ void cp_async16(void* smem, const void* gmem) {
    uint32_t s = (uint32_t)__cvta_generic_to_shared(smem);
    asm volatile("cp.async.ca.shared.global [%0], [%1], 16;" :: "r"(s), "l"(gmem));
}
__device__ __forceinline__ void cp_commit() { asm volatile("cp.async.commit_group;"); }
__device__ __forceinline__ void cp_wait0()  { asm volatile("cp.async.wait_group 0;"); }

// round-to-nearest tf32 (unbiased; applied ONCE in producers, so the GEMM
// inner loop can feed raw bits to the MMA with no cvt and no bias)
__device__ __forceinline__ float tf32r(float x) {
    uint32_t u;
    asm("cvt.rna.tf32.f32 %0, %1;" : "=r"(u) : "f"(x));
    return __uint_as_float(u);
}

__device__ __forceinline__ void mma_tf32(float* d, const float* a, const float* b) {
    asm volatile(
        "mma.sync.aligned.m16n8k8.row.col.f32.tf32.tf32.f32 "
        "{%0,%1,%2,%3}, {%4,%5,%6,%7}, {%8,%9}, {%0,%1,%2,%3};"
        : "+f"(d[0]), "+f"(d[1]), "+f"(d[2]), "+f"(d[3])
        : "r"(__float_as_uint(a[0])), "r"(__float_as_uint(a[1])),
          "r"(__float_as_uint(a[2])), "r"(__float_as_uint(a[3])),
          "r"(__float_as_uint(b[0])), "r"(__float_as_uint(b[1])));
}

// ---------------- elementwise tf32 pre-round (float4 vectorized) ------------
__global__ void preround_kernel(const float* __restrict__ in, float* __restrict__ out, int n4) {
    int i = blockIdx.x * blockDim.x + threadIdx.x;
    if (i >= n4) return;
    float4 v = reinterpret_cast<const float4*>(in)[i];
    v.x = tf32r(v.x); v.y = tf32r(v.y); v.z = tf32r(v.z); v.w = tf32r(v.w);
    reinterpret_cast<float4*>(out)[i] = v;
}

// ---------------- tf32 GEMM, cp.async double-buffered, fp16 output ---------
// Inputs pre-rounded to tf32 -> raw-bit MMA, zero cvt in the hot loop.
// BM=128, BN=64, BK=16; 256 threads, warp tile 32x32. K%16==0, N%64==0.
__global__ __launch_bounds__(256) void gemm_tf32_f16out(
    const float* __restrict__ A, const float* __restrict__ B,
    __half* __restrict__ C, int M, int N, int K)
{
    __shared__ float As[2][128][20];
    __shared__ float Bs[2][16][72];

    int tid  = threadIdx.x;
    int warp = tid >> 5, lane = tid & 31;
    int wm = (warp & 3) * 32;
    int wn = (warp >> 2) * 32;
    int m0 = blockIdx.x * 128;
    int n0 = blockIdx.y * 64;

    int r  = lane >> 2;
    int cg = lane & 3;

    int am0 = tid >> 2;
    int akq = (tid & 3) * 4;
    int bk  = tid >> 4;
    int bnq = (tid & 15) * 4;

    float acc[2][4][4];
#pragma unroll
    for (int i = 0; i < 2; i++)
#pragma unroll
        for (int j = 0; j < 4; j++)
#pragma unroll
            for (int q = 0; q < 4; q++) acc[i][j][q] = 0.f;

    int nk = K >> 4;

    {
        int gm0 = m0 + am0;       if (gm0 > M - 1) gm0 = M - 1;
        int gm1 = m0 + am0 + 64;  if (gm1 > M - 1) gm1 = M - 1;
        cp_async16(&As[0][am0     ][akq], &A[(size_t)gm0 * K + akq]);
        cp_async16(&As[0][am0 + 64][akq], &A[(size_t)gm1 * K + akq]);
        cp_async16(&Bs[0][bk][bnq], &B[(size_t)bk * N + n0 + bnq]);
        cp_commit();
    }

    for (int t = 0; t < nk; t++) {
        cp_wait0();
        __syncthreads();
        int buf = t & 1;

        if (t + 1 < nk) {
            int k0 = (t + 1) << 4;
            int gm0 = m0 + am0;       if (gm0 > M - 1) gm0 = M - 1;
            int gm1 = m0 + am0 + 64;  if (gm1 > M - 1) gm1 = M - 1;
            cp_async16(&As[buf ^ 1][am0     ][akq], &A[(size_t)gm0 * K + k0 + akq]);
            cp_async16(&As[buf ^ 1][am0 + 64][akq], &A[(size_t)gm1 * K + k0 + akq]);
            cp_async16(&Bs[buf ^ 1][bk][bnq], &B[(size_t)(k0 + bk) * N + n0 + bnq]);
            cp_commit();
        }

#pragma unroll
        for (int ks = 0; ks < 16; ks += 8) {
            float a[2][4];
#pragma unroll
            for (int mt = 0; mt < 2; mt++) {
                int mrow = wm + mt * 16 + r;
                a[mt][0] = As[buf][mrow    ][ks + cg    ];
                a[mt][1] = As[buf][mrow + 8][ks + cg    ];
                a[mt][2] = As[buf][mrow    ][ks + cg + 4];
                a[mt][3] = As[buf][mrow + 8][ks + cg + 4];
            }
            float b[4][2];
#pragma unroll
            for (int nt = 0; nt < 4; nt++) {
                b[nt][0] = Bs[buf][ks + cg    ][wn + nt * 8 + r];
                b[nt][1] = Bs[buf][ks + cg + 4][wn + nt * 8 + r];
            }
#pragma unroll
            for (int mt = 0; mt < 2; mt++)
#pragma unroll
                for (int nt = 0; nt < 4; nt++)
                    mma_tf32(acc[mt][nt], a[mt], b[nt]);
        }
        __syncthreads();
    }

#pragma unroll
    for (int mt = 0; mt < 2; mt++) {
#pragma unroll
        for (int nt = 0; nt < 4; nt++) {
            int row = m0 + wm + mt * 16 + r;
            int col = n0 + wn + nt * 8 + 2 * cg;
            if (row < M) {
                __half2 o = __floats2half2_rn(acc[mt][nt][0], acc[mt][nt][1]);
                *reinterpret_cast<__half2*>(&C[(size_t)row * N + col]) = o;
            }
            if (row + 8 < M) {
                __half2 o = __floats2half2_rn(acc[mt][nt][2], acc[mt][nt][3]);
                *reinterpret_cast<__half2*>(&C[(size_t)(row + 8) * N + col]) = o;
            }
        }
    }
}

// ---------------- CSR build: histogram -> scan -> scatter -------------------
__global__ void hist_kernel(const int* __restrict__ ei, int* __restrict__ deg,
                            int E, int N) {
    int e = blockIdx.x * blockDim.x + threadIdx.x;
    if (e >= E + N) return;
    int d = (e < E) ? ei[E + e] : (e - E);
    atomicAdd(&deg[d], 1);
}

__global__ void scan_kernel(const int* __restrict__ deg, int* __restrict__ rowptr,
                            int* __restrict__ rowpos, int N) {
    __shared__ int sums[1024];
    int t = threadIdx.x;
    int CH = (N + 1023) / 1024;
    int b = t * CH, e = min(N, b + CH);
    int s = 0;
    for (int i = b; i < e; i++) s += deg[i];
    sums[t] = s;
    __syncthreads();
    for (int off = 1; off < 1024; off <<= 1) {
        int v = (t >= off) ? sums[t - off] : 0;
        __syncthreads();
        sums[t] += v;
        __syncthreads();
    }
    int run = (t == 0) ? 0 : sums[t - 1];
    for (int i = b; i < e; i++) {
        rowptr[i] = run;
        rowpos[i] = run;
        run += deg[i];
    }
    if (t == 1023) rowptr[N] = sums[1023];
}

__global__ void scatter_kernel(const int* __restrict__ ei, int* __restrict__ rowpos,
                               int* __restrict__ csrsrc, int E, int N) {
    int e = blockIdx.x * blockDim.x + threadIdx.x;
    if (e >= E + N) return;
    int s, d;
    if (e < E) { s = ei[e]; d = ei[E + e]; } else { s = d = e - E; }
    int pos = atomicAdd(&rowpos[d], 1);
    csrsrc[pos] = s;
}

// ---------------- per-node attention logits (fp16 features) ----------------
template<int C>
__global__ void alpha_kernel(const __half* __restrict__ h,
                             const float* __restrict__ asr, const float* __restrict__ adt,
                             float* __restrict__ outs, float* __restrict__ outd, int N) {
    int idx = blockIdx.x * blockDim.x + threadIdx.x;
    if (idx >= N * NHEAD) return;
    int hh = idx & (NHEAD - 1);
    const __half* hp = h + (size_t)idx * C;
    const float* ap = asr + hh * C;
    const float* dp = adt + hh * C;
    float ss = 0.f, dd = 0.f;
#pragma unroll
    for (int i = 0; i < C; i += 8) {
        uint4 raw = *reinterpret_cast<const uint4*>(hp + i);
        float2 f0 = __half22float2(*reinterpret_cast<__half2*>(&raw.x));
        float2 f1 = __half22float2(*reinterpret_cast<__half2*>(&raw.y));
        float2 f2 = __half22float2(*reinterpret_cast<__half2*>(&raw.z));
        float2 f3 = __half22float2(*reinterpret_cast<__half2*>(&raw.w));
        float4 a0 = *reinterpret_cast<const float4*>(ap + i);
        float4 a1 = *reinterpret_cast<const float4*>(ap + i + 4);
        float4 d0 = *reinterpret_cast<const float4*>(dp + i);
        float4 d1 = *reinterpret_cast<const float4*>(dp + i + 4);
        ss += f0.x * a0.x + f0.y * a0.y + f1.x * a0.z + f1.y * a0.w
            + f2.x * a1.x + f2.y * a1.y + f3.x * a1.z + f3.y * a1.w;
        dd += f0.x * d0.x + f0.y * d0.y + f1.x * d0.z + f1.y * d0.w
            + f2.x * d1.x + f2.y * d1.y + f3.x * d1.z + f3.y * d1.w;
    }
    outs[idx] = ss;
    outd[idx] = dd;
}

// ---------------- pull aggregation layer 1 (warp per dst, all heads) -------
// fp16 gather (16B/lane/edge). Lane owns 8 channels; head = lane>>3.
// Fused softmax denom + bias + relu + tf32 rounding (GEMM2 consumes raw bits).
__global__ void agg1_kernel(const int* __restrict__ rowptr, const int* __restrict__ csrsrc,
                            const float* __restrict__ as, const float* __restrict__ ad,
                            const __half* __restrict__ h,
                            const float* __restrict__ bias, float* __restrict__ out, int N) {
    int gw = (blockIdx.x * blockDim.x + threadIdx.x) >> 5;
    int lane = threadIdx.x & 31;
    if (gw >= N) return;
    int hh = lane >> 3;
    int beg = rowptr[gw], end = rowptr[gw + 1];
    float adh = ad[(size_t)gw * 4 + hh];
    float4 acc0 = make_float4(0.f, 0.f, 0.f, 0.f);
    float4 acc1 = make_float4(0.f, 0.f, 0.f, 0.f);
    float wsum = 0.f;
    for (int i = beg; i < end; i++) {
        int s = csrsrc[i];                      // warp-uniform broadcast
        float asv = as[(size_t)s * 4 + hh];     // 4 distinct addrs per warp
        float t = asv + adh; t = t > 0.f ? t : NEG_SLOPE * t;
        float w = __expf(t);
        wsum += w;
        uint4 raw = *reinterpret_cast<const uint4*>(h + (size_t)s * F1 + lane * 8);
        float2 f0 = __half22float2(*reinterpret_cast<__half2*>(&raw.x));
        float2 f1 = __half22float2(*reinterpret_cast<__half2*>(&raw.y));
        float2 f2 = __half22float2(*reinterpret_cast<__half2*>(&raw.z));
        float2 f3 = __half22float2(*reinterpret_cast<__half2*>(&raw.w));
        acc0.x += w * f0.x; acc0.y += w * f0.y; acc0.z += w * f1.x; acc0.w += w * f1.y;
        acc1.x += w * f2.x; acc1.y += w * f2.y; acc1.z += w * f3.x; acc1.w += w * f3.y;
    }
    float inv = 1.f / wsum;
    int c = lane * 8;
    const float4* bp = reinterpret_cast<const float4*>(bias + c);
    float4 b0 = bp[0], b1 = bp[1];
    float4 o0, o1;
    o0.x = tf32r(fmaxf(acc0.x * inv + b0.x, 0.f)); o0.y = tf32r(fmaxf(acc0.y * inv + b0.y, 0.f));
    o0.z = tf32r(fmaxf(acc0.z * inv + b0.z, 0.f)); o0.w = tf32r(fmaxf(acc0.w * inv + b0.w, 0.f));
    o1.x = tf32r(fmaxf(acc1.x * inv + b1.x, 0.f)); o1.y = tf32r(fmaxf(acc1.y * inv + b1.y, 0.f));
    o1.z = tf32r(fmaxf(acc1.z * inv + b1.z, 0.f)); o1.w = tf32r(fmaxf(acc1.w * inv + b1.w, 0.f));
    float4* op = reinterpret_cast<float4*>(out + (size_t)gw * F1 + c);
    op[0] = o0; op[1] = o1;
}

// ---------------- pull aggregation layer 2 (warp per dst node) -------------
// fp16 gather (4B/lane/edge). Lane owns 2 channels; head = lane>>3.
__global__ void agg2_kernel(const int* __restrict__ rowptr, const int* __restrict__ csrsrc,
                            const float* __restrict__ as, const float* __restrict__ ad,
                            const __half* __restrict__ h,
                            const float* __restrict__ bias, float* __restrict__ out, int N) {
    int gw = (blockIdx.x * blockDim.x + threadIdx.x) >> 5;
    int lane = threadIdx.x & 31;
    if (gw >= N) return;
    int hh = lane >> 3;
    int beg = rowptr[gw], end = rowptr[gw + 1];
    float adh = ad[(size_t)gw * 4 + hh];
    float acc0 = 0.f, acc1 = 0.f, wsum = 0.f;
    for (int i = beg; i < end; i++) {
        int s = csrsrc[i];
        float asv = as[(size_t)s * 4 + hh];
        float t = asv + adh; t = t > 0.f ? t : NEG_SLOPE * t;
        float w = __expf(t);
        wsum += w;
        __half2 hv = *reinterpret_cast<const __half2*>(h + (size_t)s * F2 + lane * 2);
        float2 v = __half22float2(hv);
        acc0 += w * v.x;
        acc1 += w * v.y;
    }
    float inv = 1.f / wsum;
    int c = lane * 2;
    float o0 = acc0 * inv + bias[c];
    float o1 = acc1 * inv + bias[c + 1];
    float2 o = make_float2(o0 > 0.f ? o0 : 0.f, o1 > 0.f ? o1 : 0.f);
    *reinterpret_cast<float2*>(out + (size_t)gw * F2 + c) = o;
}

// ---------------- pooling (batch sorted -> run-length accumulation) --------
__global__ void pool_kernel(const float* __restrict__ g, const int* __restrict__ batch,
                            float* __restrict__ pool, int N) {
    int c = blockIdx.y;
    int t = blockIdx.x * blockDim.x + threadIdx.x;
    const int CH = 64;
    int n0 = t * CH;
    if (n0 >= N) return;
    int n1 = min(N, n0 + CH);
    int cur = batch[n0];
    float acc = 0.f;
    for (int n = n0; n < n1; n++) {
        int bb = batch[n];
        if (bb != cur) { atomicAdd(&pool[cur * F2 + c], acc); cur = bb; acc = 0.f; }
        acc += g[(size_t)n * F2 + c];
    }
    atomicAdd(&pool[cur * F2 + c], acc);
}

__global__ void count_kernel(const int* __restrict__ batch, float* __restrict__ cnt, int N) {
    int t = blockIdx.x * blockDim.x + threadIdx.x;
    const int CH = 64;
    int n0 = t * CH;
    if (n0 >= N) return;
    int n1 = min(N, n0 + CH);
    int cur = batch[n0];
    float acc = 0.f;
    for (int n = n0; n < n1; n++) {
        int bb = batch[n];
        if (bb != cur) { atomicAdd(&cnt[cur], acc); cur = bb; acc = 0.f; }
        acc += 1.f;
    }
    atomicAdd(&cnt[cur], acc);
}

// ---------------- final FC --------------------------------------------------
__global__ void fc_kernel(const float* __restrict__ pool, const float* __restrict__ cnt,
                          const float* __restrict__ w, const float* __restrict__ b,
                          float* __restrict__ out) {
    int g = blockIdx.x;
    int j = threadIdx.x;
    float inv = 1.f / fmaxf(cnt[g], 1.f);
    float acc = b[j];
#pragma unroll
    for (int c = 0; c < F2; c++)
        acc += pool[g * F2 + c] * inv * w[c * NOUT + j];
    out[g * NOUT + j] = acc;
}

// ---------------- launch ----------------------------------------------------
extern "C" void kernel_launch(void* const* d_in, const int* in_sizes, int n_in,
                              void* d_out, int out_size) {
    const float* x      = (const float*)d_in[0];
    const int*   ei     = (const int*)  d_in[1];
    const int*   batch  = (const int*)  d_in[2];
    const float* W1     = (const float*)d_in[3];
    const float* a_src1 = (const float*)d_in[4];
    const float* a_dst1 = (const float*)d_in[5];
    const float* b1     = (const float*)d_in[6];
    const float* W2     = (const float*)d_in[7];
    const float* a_src2 = (const float*)d_in[8];
    const float* a_dst2 = (const float*)d_in[9];
    const float* b2     = (const float*)d_in[10];
    const float* fcw    = (const float*)d_in[11];
    const float* fcb    = (const float*)d_in[12];

    int N = in_sizes[0] / F0;     // 50000
    int E = in_sizes[1] / 2;      // 800000
    int ET = E + N;

    __half *p_h1, *p_h2;
    float *p_g1, *p_g2, *p_w1r, *p_w2r, *p_as, *p_ad, *p_pool, *p_cnt;
    int *p_deg, *p_rowptr, *p_rowpos, *p_csrsrc;
    cudaGetSymbolAddress((void**)&p_h1, d_h1);
    cudaGetSymbolAddress((void**)&p_g1, d_g1);
    cudaGetSymbolAddress((void**)&p_h2, d_h2);
    cudaGetSymbolAddress((void**)&p_g2, d_g2);
    cudaGetSymbolAddress((void**)&p_w1r, d_w1r);
    cudaGetSymbolAddress((void**)&p_w2r, d_w2r);
    cudaGetSymbolAddress((void**)&p_as, d_as);
    cudaGetSymbolAddress((void**)&p_ad, d_ad);
    cudaGetSymbolAddress((void**)&p_deg, d_deg);
    cudaGetSymbolAddress((void**)&p_rowptr, d_rowptr);
    cudaGetSymbolAddress((void**)&p_rowpos, d_rowpos);
    cudaGetSymbolAddress((void**)&p_csrsrc, d_csrsrc);
    cudaGetSymbolAddress((void**)&p_pool, d_pool);
    cudaGetSymbolAddress((void**)&p_cnt, d_cnt);

    float* out = (float*)d_out;
    float* p_xr = p_g1;   // reuse g1 storage for tf32-rounded x (free until agg1)

    // ---------------- CSR build (shared by both layers) ----------------
    cudaMemsetAsync(p_deg, 0, (size_t)N * sizeof(int));
    hist_kernel<<<(ET + 255) / 256, 256>>>(ei, p_deg, E, N);
    scan_kernel<<<1, 1024>>>(p_deg, p_rowptr, p_rowpos, N);
    scatter_kernel<<<(ET + 255) / 256, 256>>>(ei, p_rowpos, p_csrsrc, E, N);

    // ---------------- tf32 pre-rounding ----------------
    preround_kernel<<<((N * F0 / 4) + 255) / 256, 256>>>(x, p_xr, N * F0 / 4);
    preround_kernel<<<((F0 * F1 / 4) + 255) / 256, 256>>>(W1, p_w1r, F0 * F1 / 4);
    preround_kernel<<<((F1 * F2 / 4) + 255) / 256, 256>>>(W2, p_w2r, F1 * F2 / 4);

    // ---------------- layer 1 ----------------
    {
        dim3 grid((N + 127) / 128, F1 / 64);
        gemm_tf32_f16out<<<grid, 256>>>(p_xr, p_w1r, p_h1, N, F1, F0);
    }
    alpha_kernel<C1><<<(N * NHEAD + 255) / 256, 256>>>(p_h1, a_src1, a_dst1, p_as, p_ad, N);
    agg1_kernel<<<(N * 32 + 255) / 256, 256>>>(p_rowptr, p_csrsrc, p_as, p_ad,
                                               p_h1, b1, p_g1, N);

    // ---------------- layer 2 ----------------
    {
        dim3 grid((N + 127) / 128, F2 / 64);
        gemm_tf32_f16out<<<grid, 256>>>(p_g1, p_w2r, p_h2, N, F2, F1);
    }
    alpha_kernel<C2><<<(N * NHEAD + 255) / 256, 256>>>(p_h2, a_src2, a_dst2, p_as, p_ad, N);
    agg2_kernel<<<(N * 32 + 255) / 256, 256>>>(p_rowptr, p_csrsrc, p_as, p_ad,
                                               p_h2, b2, p_g2, N);

    // ---------------- pooling + FC ----------------
    cudaMemsetAsync(p_pool, 0, (size_t)NG * F2 * sizeof(float));
    cudaMemsetAsync(p_cnt, 0, (size_t)NG * sizeof(float));
    {
        int nthreads = (N + 63) / 64;
        dim3 grid((nthreads + 127) / 128, F2);
        pool_kernel<<<grid, 128>>>(p_g2, batch, p_pool, N);
        count_kernel<<<(nthreads + 127) / 128, 128>>>(batch, p_cnt, N);
    }
    fc_kernel<<<NG, NOUT>>>(p_pool, p_cnt, fcw, fcb, out);
}

// round 11
// speedup vs baseline: 2.0150x; 1.0526x over previous
#include <cuda_runtime.h>
#include <cuda_fp16.h>
#include <cstdint>

// ---------------- problem constants (fixed by setup_inputs) ----------------
#define NN   50000
#define EE   800000
#define ET_MAX (EE+NN)
#define F0   128
#define NHEAD 4
#define C1   64
#define F1   (NHEAD*C1)   // 256
#define C2   16
#define F2   (NHEAD*C2)   // 64
#define NG   64
#define NOUT 32
#define NEG_SLOPE 0.2f

// ---------------- scratch (device globals; no allocation allowed) ----------
__device__ __half d_x16[NN*F0];        // fp16 input features (12.8 MB)
__device__ __half d_w1h[F0*F1];        // fp16 W1
__device__ __half d_w2h[F1*F2];        // fp16 W2
__device__ __half d_h1[NN*F1];         // layer1 features, fp16 (25.6 MB)
__device__ __half d_g1h[NN*F1];        // layer1 aggregated, fp16 (GEMM2 input)
__device__ __half d_h2[NN*F2];         // layer2 features, fp16
__device__ float  d_g2[NN*F2];
__device__ float  d_as[NN*NHEAD];
__device__ float  d_ad[NN*NHEAD];
__device__ int    d_deg[NN];
__device__ int    d_rowptr[NN+1];
__device__ int    d_rowpos[NN];
__device__ int    d_csrsrc[ET_MAX];
__device__ float  d_pool[NG*F2];
__device__ float  d_cnt[NG];

// ---------------- helpers ---------------------------------------------------
__device__ __forceinline__ void cp_async16(void* smem, const void* gmem) {
    uint32_t s = (uint32_t)__cvta_generic_to_shared(smem);
    asm volatile("cp.async.ca.shared.global [%0], [%1], 16;" :: "r"(s), "l"(gmem));
}
__device__ __forceinline__ void cp_commit() { asm volatile("cp.async.commit_group;"); }
__device__ __forceinline__ void cp_wait0()  { asm volatile("cp.async.wait_group 0;"); }

__device__ __forceinline__ uint32_t smem_u32(const void* p) {
    return (uint32_t)__cvta_generic_to_shared(p);
}
__device__ __forceinline__ void ldsm_x4(uint32_t& r0, uint32_t& r1, uint32_t& r2, uint32_t& r3,
                                        uint32_t addr) {
    asm volatile("ldmatrix.sync.aligned.m8n8.x4.shared.b16 {%0,%1,%2,%3}, [%4];"
                 : "=r"(r0), "=r"(r1), "=r"(r2), "=r"(r3) : "r"(addr));
}
__device__ __forceinline__ void ldsm_x4_t(uint32_t& r0, uint32_t& r1, uint32_t& r2, uint32_t& r3,
                                          uint32_t addr) {
    asm volatile("ldmatrix.sync.aligned.m8n8.x4.trans.shared.b16 {%0,%1,%2,%3}, [%4];"
                 : "=r"(r0), "=r"(r1), "=r"(r2), "=r"(r3) : "r"(addr));
}
__device__ __forceinline__ void mma_f16(float* d, uint32_t a0, uint32_t a1, uint32_t a2,
                                        uint32_t a3, uint32_t b0, uint32_t b1) {
    asm volatile(
        "mma.sync.aligned.m16n8k16.row.col.f32.f16.f16.f32 "
        "{%0,%1,%2,%3}, {%4,%5,%6,%7}, {%8,%9}, {%0,%1,%2,%3};"
        : "+f"(d[0]), "+f"(d[1]), "+f"(d[2]), "+f"(d[3])
        : "r"(a0), "r"(a1), "r"(a2), "r"(a3), "r"(b0), "r"(b1));
}

// ---------------- fp32 -> fp16 convert (4 elems/thread) ---------------------
__global__ void f2h_kernel(const float4* __restrict__ in, uint2* __restrict__ out, int n4) {
    int i = blockIdx.x * blockDim.x + threadIdx.x;
    if (i >= n4) return;
    float4 v = in[i];
    __half2 a = __floats2half2_rn(v.x, v.y);
    __half2 b = __floats2half2_rn(v.z, v.w);
    uint2 o;
    o.x = *reinterpret_cast<uint32_t*>(&a);
    o.y = *reinterpret_cast<uint32_t*>(&b);
    out[i] = o;
}

// ---------------- fp16 HMMA GEMM: C[M,N] = A[M,K] @ B[K,N] -----------------
// BM=128, BN=64, BK=32 halves; 256 threads = 8 warps (4M x 2N), warp 32x32.
// cp.async double-buffered; ldmatrix fragments. K%32==0, N%64==0.
__global__ __launch_bounds__(256) void gemm_f16(
    const __half* __restrict__ A, const __half* __restrict__ B,
    __half* __restrict__ C, int M, int N, int K)
{
    __shared__ __half As[2][128][40];   // [m][k], pad 40 halves (80B: LDSM conflict-free)
    __shared__ __half Bs[2][32][72];    // [k][n], pad 72 halves (144B: LDSM conflict-free)

    int tid  = threadIdx.x;
    int warp = tid >> 5, lane = tid & 31;
    int wm = (warp & 3) * 32;
    int wn = (warp >> 2) * 32;
    int m0 = blockIdx.x * 128;
    int n0 = blockIdx.y * 64;

    int r  = lane >> 2;
    int cg = lane & 3;
    int g  = lane >> 3;        // ldmatrix tile group 0..3
    int lr = lane & 7;
    int rowoff = (g & 1) * 8 + lr;   // row offset within 16-row span
    int coloff = (g >> 1) * 8;       // col offset within 16-col span

    // load coords: A 512x16B chunks (2/thread), B 256x16B chunks (1/thread)
    int arow = tid >> 2;             // 0..63 (and +64)
    int akc  = (tid & 3) * 8;        // k offset in halves
    int brow = tid >> 3;             // 0..31
    int bnc  = (tid & 7) * 8;        // n offset in halves

    float acc[2][4][4];
#pragma unroll
    for (int i = 0; i < 2; i++)
#pragma unroll
        for (int j = 0; j < 4; j++)
#pragma unroll
            for (int q = 0; q < 4; q++) acc[i][j][q] = 0.f;

    int nk = K >> 5;

    {
        int gm0 = m0 + arow;       if (gm0 > M - 1) gm0 = M - 1;
        int gm1 = m0 + arow + 64;  if (gm1 > M - 1) gm1 = M - 1;
        cp_async16(&As[0][arow     ][akc], &A[(size_t)gm0 * K + akc]);
        cp_async16(&As[0][arow + 64][akc], &A[(size_t)gm1 * K + akc]);
        cp_async16(&Bs[0][brow][bnc], &B[(size_t)brow * N + n0 + bnc]);
        cp_commit();
    }

    for (int t = 0; t < nk; t++) {
        cp_wait0();
        __syncthreads();
        int buf = t & 1;

        if (t + 1 < nk) {
            int k0 = (t + 1) << 5;
            int gm0 = m0 + arow;       if (gm0 > M - 1) gm0 = M - 1;
            int gm1 = m0 + arow + 64;  if (gm1 > M - 1) gm1 = M - 1;
            cp_async16(&As[buf ^ 1][arow     ][akc], &A[(size_t)gm0 * K + k0 + akc]);
            cp_async16(&As[buf ^ 1][arow + 64][akc], &A[(size_t)gm1 * K + k0 + akc]);
            cp_async16(&Bs[buf ^ 1][brow][bnc], &B[(size_t)(k0 + brow) * N + n0 + bnc]);
            cp_commit();
        }

#pragma unroll
        for (int ks = 0; ks < 32; ks += 16) {
            uint32_t a[2][4];
#pragma unroll
            for (int mt = 0; mt < 2; mt++)
                ldsm_x4(a[mt][0], a[mt][1], a[mt][2], a[mt][3],
                        smem_u32(&As[buf][wm + mt * 16 + rowoff][ks + coloff]));
            uint32_t b[4][2];
#pragma unroll
            for (int np = 0; np < 2; np++) {
                uint32_t r0, r1, r2, r3;
                ldsm_x4_t(r0, r1, r2, r3,
                          smem_u32(&Bs[buf][ks + rowoff][wn + np * 16 + coloff]));
                b[np * 2][0] = r0; b[np * 2][1] = r1;
                b[np * 2 + 1][0] = r2; b[np * 2 + 1][1] = r3;
            }
#pragma unroll
            for (int mt = 0; mt < 2; mt++)
#pragma unroll
                for (int nt = 0; nt < 4; nt++)
                    mma_f16(acc[mt][nt], a[mt][0], a[mt][1], a[mt][2], a[mt][3],
                            b[nt][0], b[nt][1]);
        }
        __syncthreads();
    }

#pragma unroll
    for (int mt = 0; mt < 2; mt++) {
#pragma unroll
        for (int nt = 0; nt < 4; nt++) {
            int row = m0 + wm + mt * 16 + r;
            int col = n0 + wn + nt * 8 + 2 * cg;
            if (row < M) {
                __half2 o = __floats2half2_rn(acc[mt][nt][0], acc[mt][nt][1]);
                *reinterpret_cast<__half2*>(&C[(size_t)row * N + col]) = o;
            }
            if (row + 8 < M) {
                __half2 o = __floats2half2_rn(acc[mt][nt][2], acc[mt][nt][3]);
                *reinterpret_cast<__half2*>(&C[(size_t)(row + 8) * N + col]) = o;
            }
        }
    }
}

// ---------------- CSR build: histogram -> scan -> scatter -------------------
__global__ void hist_kernel(const int* __restrict__ ei, int* __restrict__ deg,
                            int E, int N) {
    int e = blockIdx.x * blockDim.x + threadIdx.x;
    if (e >= E + N) return;
    int d = (e < E) ? ei[E + e] : (e - E);
    atomicAdd(&deg[d], 1);
}

__global__ void scan_kernel(const int* __restrict__ deg, int* __restrict__ rowptr,
                            int* __restrict__ rowpos, int N) {
    __shared__ int sums[1024];
    int t = threadIdx.x;
    int CH = (N + 1023) / 1024;
    int b = t * CH, e = min(N, b + CH);
    int s = 0;
    for (int i = b; i < e; i++) s += deg[i];
    sums[t] = s;
    __syncthreads();
    for (int off = 1; off < 1024; off <<= 1) {
        int v = (t >= off) ? sums[t - off] : 0;
        __syncthreads();
        sums[t] += v;
        __syncthreads();
    }
    int run = (t == 0) ? 0 : sums[t - 1];
    for (int i = b; i < e; i++) {
        rowptr[i] = run;
        rowpos[i] = run;
        run += deg[i];
    }
    if (t == 1023) rowptr[N] = sums[1023];
}

__global__ void scatter_kernel(const int* __restrict__ ei, int* __restrict__ rowpos,
                               int* __restrict__ csrsrc, int E, int N) {
    int e = blockIdx.x * blockDim.x + threadIdx.x;
    if (e >= E + N) return;
    int s, d;
    if (e < E) { s = ei[e]; d = ei[E + e]; } else { s = d = e - E; }
    int pos = atomicAdd(&rowpos[d], 1);
    csrsrc[pos] = s;
}

// ---------------- per-node attention logits (fp16 features) ----------------
template<int C>
__global__ void alpha_kernel(const __half* __restrict__ h,
                             const float* __restrict__ asr, const float* __restrict__ adt,
                             float* __restrict__ outs, float* __restrict__ outd, int N) {
    int idx = blockIdx.x * blockDim.x + threadIdx.x;
    if (idx >= N * NHEAD) return;
    int hh = idx & (NHEAD - 1);
    const __half* hp = h + (size_t)idx * C;
    const float* ap = asr + hh * C;
    const float* dp = adt + hh * C;
    float ss = 0.f, dd = 0.f;
#pragma unroll
    for (int i = 0; i < C; i += 8) {
        uint4 raw = *reinterpret_cast<const uint4*>(hp + i);
        float2 f0 = __half22float2(*reinterpret_cast<__half2*>(&raw.x));
        float2 f1 = __half22float2(*reinterpret_cast<__half2*>(&raw.y));
        float2 f2 = __half22float2(*reinterpret_cast<__half2*>(&raw.z));
        float2 f3 = __half22float2(*reinterpret_cast<__half2*>(&raw.w));
        float4 a0 = *reinterpret_cast<const float4*>(ap + i);
        float4 a1 = *reinterpret_cast<const float4*>(ap + i + 4);
        float4 d0 = *reinterpret_cast<const float4*>(dp + i);
        float4 d1 = *reinterpret_cast<const float4*>(dp + i + 4);
        ss += f0.x * a0.x + f0.y * a0.y + f1.x * a0.z + f1.y * a0.w
            + f2.x * a1.x + f2.y * a1.y + f3.x * a1.z + f3.y * a1.w;
        dd += f0.x * d0.x + f0.y * d0.y + f1.x * d0.z + f1.y * d0.w
            + f2.x * d1.x + f2.y * d1.y + f3.x * d1.z + f3.y * d1.w;
    }
    outs[idx] = ss;
    outd[idx] = dd;
}

// ---------------- pull aggregation layer 1 (warp per dst, all heads) -------
// fp16 gather; lane owns 8 channels; head = lane>>3. Fused denom+bias+relu.
// Output fp16 (consumed only by GEMM2).
__global__ void agg1_kernel(const int* __restrict__ rowptr, const int* __restrict__ csrsrc,
                            const float* __restrict__ as, const float* __restrict__ ad,
                            const __half* __restrict__ h,
                            const float* __restrict__ bias, __half* __restrict__ out, int N) {
    int gw = (blockIdx.x * blockDim.x + threadIdx.x) >> 5;
    int lane = threadIdx.x & 31;
    if (gw >= N) return;
    int hh = lane >> 3;
    int beg = rowptr[gw], end = rowptr[gw + 1];
    float adh = ad[(size_t)gw * 4 + hh];
    float4 acc0 = make_float4(0.f, 0.f, 0.f, 0.f);
    float4 acc1 = make_float4(0.f, 0.f, 0.f, 0.f);
    float wsum = 0.f;
    int s = (beg < end) ? csrsrc[beg] : 0;
    for (int i = beg; i < end; i++) {
        int snext = (i + 1 < end) ? csrsrc[i + 1] : 0;   // prefetch index
        float asv = as[(size_t)s * 4 + hh];
        float t = asv + adh; t = t > 0.f ? t : NEG_SLOPE * t;
        float w = __expf(t);
        wsum += w;
        uint4 raw = *reinterpret_cast<const uint4*>(h + (size_t)s * F1 + lane * 8);
        float2 f0 = __half22float2(*reinterpret_cast<__half2*>(&raw.x));
        float2 f1 = __half22float2(*reinterpret_cast<__half2*>(&raw.y));
        float2 f2 = __half22float2(*reinterpret_cast<__half2*>(&raw.z));
        float2 f3 = __half22float2(*reinterpret_cast<__half2*>(&raw.w));
        acc0.x += w * f0.x; acc0.y += w * f0.y; acc0.z += w * f1.x; acc0.w += w * f1.y;
        acc1.x += w * f2.x; acc1.y += w * f2.y; acc1.z += w * f3.x; acc1.w += w * f3.y;
        s = snext;
    }
    float inv = 1.f / wsum;
    int c = lane * 8;
    const float4* bp = reinterpret_cast<const float4*>(bias + c);
    float4 b0 = bp[0], b1 = bp[1];
    __half2 p0 = __floats2half2_rn(fmaxf(acc0.x * inv + b0.x, 0.f), fmaxf(acc0.y * inv + b0.y, 0.f));
    __half2 p1 = __floats2half2_rn(fmaxf(acc0.z * inv + b0.z, 0.f), fmaxf(acc0.w * inv + b0.w, 0.f));
    __half2 p2 = __floats2half2_rn(fmaxf(acc1.x * inv + b1.x, 0.f), fmaxf(acc1.y * inv + b1.y, 0.f));
    __half2 p3 = __floats2half2_rn(fmaxf(acc1.z * inv + b1.z, 0.f), fmaxf(acc1.w * inv + b1.w, 0.f));
    uint4 o;
    o.x = *reinterpret_cast<uint32_t*>(&p0);
    o.y = *reinterpret_cast<uint32_t*>(&p1);
    o.z = *reinterpret_cast<uint32_t*>(&p2);
    o.w = *reinterpret_cast<uint32_t*>(&p3);
    *reinterpret_cast<uint4*>(out + (size_t)gw * F1 + c) = o;
}

// ---------------- pull aggregation layer 2 (warp per dst node) -------------
__global__ void agg2_kernel(const int* __restrict__ rowptr, const int* __restrict__ csrsrc,
                            const float* __restrict__ as, const float* __restrict__ ad,
                            const __half* __restrict__ h,
                            const float* __restrict__ bias, float* __restrict__ out, int N) {
    int gw = (blockIdx.x * blockDim.x + threadIdx.x) >> 5;
    int lane = threadIdx.x & 31;
    if (gw >= N) return;
    int hh = lane >> 3;
    int beg = rowptr[gw], end = rowptr[gw + 1];
    float adh = ad[(size_t)gw * 4 + hh];
    float acc0 = 0.f, acc1 = 0.f, wsum = 0.f;
    int s = (beg < end) ? csrsrc[beg] : 0;
    for (int i = beg; i < end; i++) {
        int snext = (i + 1 < end) ? csrsrc[i + 1] : 0;
        float asv = as[(size_t)s * 4 + hh];
        float t = asv + adh; t = t > 0.f ? t : NEG_SLOPE * t;
        float w = __expf(t);
        wsum += w;
        __half2 hv = *reinterpret_cast<const __half2*>(h + (size_t)s * F2 + lane * 2);
        float2 v = __half22float2(hv);
        acc0 += w * v.x;
        acc1 += w * v.y;
        s = snext;
    }
    float inv = 1.f / wsum;
    int c = lane * 2;
    float o0 = acc0 * inv + bias[c];
    float o1 = acc1 * inv + bias[c + 1];
    float2 o = make_float2(o0 > 0.f ? o0 : 0.f, o1 > 0.f ? o1 : 0.f);
    *reinterpret_cast<float2*>(out + (size_t)gw * F2 + c) = o;
}

// ---------------- pooling (batch sorted -> run-length accumulation) --------
__global__ void pool_kernel(const float* __restrict__ g, const int* __restrict__ batch,
                            float* __restrict__ pool, int N) {
    int c = blockIdx.y;
    int t = blockIdx.x * blockDim.x + threadIdx.x;
    const int CH = 64;
    int n0 = t * CH;
    if (n0 >= N) return;
    int n1 = min(N, n0 + CH);
    int cur = batch[n0];
    float acc = 0.f;
    for (int n = n0; n < n1; n++) {
        int bb = batch[n];
        if (bb != cur) { atomicAdd(&pool[cur * F2 + c], acc); cur = bb; acc = 0.f; }
        acc += g[(size_t)n * F2 + c];
    }
    atomicAdd(&pool[cur * F2 + c], acc);
}

__global__ void count_kernel(const int* __restrict__ batch, float* __restrict__ cnt, int N) {
    int t = blockIdx.x * blockDim.x + threadIdx.x;
    const int CH = 64;
    int n0 = t * CH;
    if (n0 >= N) return;
    int n1 = min(N, n0 + CH);
    int cur = batch[n0];
    float acc = 0.f;
    for (int n = n0; n < n1; n++) {
        int bb = batch[n];
        if (bb != cur) { atomicAdd(&cnt[cur], acc); cur = bb; acc = 0.f; }
        acc += 1.f;
    }
    atomicAdd(&cnt[cur], acc);
}

// ---------------- final FC --------------------------------------------------
__global__ void fc_kernel(const float* __restrict__ pool, const float* __restrict__ cnt,
                          const float* __restrict__ w, const float* __restrict__ b,
                          float* __restrict__ out) {
    int g = blockIdx.x;
    int j = threadIdx.x;
    float inv = 1.f / fmaxf(cnt[g], 1.f);
    float acc = b[j];
#pragma unroll
    for (int c = 0; c < F2; c++)
        acc += pool[g * F2 + c] * inv * w[c * NOUT + j];
    out[g * NOUT + j] = acc;
}

// ---------------- launch ----------------------------------------------------
extern "C" void kernel_launch(void* const* d_in, const int* in_sizes, int n_in,
                              void* d_out, int out_size) {
    const float* x      = (const float*)d_in[0];
    const int*   ei     = (const int*)  d_in[1];
    const int*   batch  = (const int*)  d_in[2];
    const float* W1     = (const float*)d_in[3];
    const float* a_src1 = (const float*)d_in[4];
    const float* a_dst1 = (const float*)d_in[5];
    const float* b1     = (const float*)d_in[6];
    const float* W2     = (const float*)d_in[7];
    const float* a_src2 = (const float*)d_in[8];
    const float* a_dst2 = (const float*)d_in[9];
    const float* b2     = (const float*)d_in[10];
    const float* fcw    = (const float*)d_in[11];
    const float* fcb    = (const float*)d_in[12];

    int N = in_sizes[0] / F0;     // 50000
    int E = in_sizes[1] / 2;      // 800000
    int ET = E + N;

    __half *p_x16, *p_w1h, *p_w2h, *p_h1, *p_g1h, *p_h2;
    float *p_g2, *p_as, *p_ad, *p_pool, *p_cnt;
    int *p_deg, *p_rowptr, *p_rowpos, *p_csrsrc;
    cudaGetSymbolAddress((void**)&p_x16, d_x16);
    cudaGetSymbolAddress((void**)&p_w1h, d_w1h);
    cudaGetSymbolAddress((void**)&p_w2h, d_w2h);
    cudaGetSymbolAddress((void**)&p_h1, d_h1);
    cudaGetSymbolAddress((void**)&p_g1h, d_g1h);
    cudaGetSymbolAddress((void**)&p_h2, d_h2);
    cudaGetSymbolAddress((void**)&p_g2, d_g2);
    cudaGetSymbolAddress((void**)&p_as, d_as);
    cudaGetSymbolAddress((void**)&p_ad, d_ad);
    cudaGetSymbolAddress((void**)&p_deg, d_deg);
    cudaGetSymbolAddress((void**)&p_rowptr, d_rowptr);
    cudaGetSymbolAddress((void**)&p_rowpos, d_rowpos);
    cudaGetSymbolAddress((void**)&p_csrsrc, d_csrsrc);
    cudaGetSymbolAddress((void**)&p_pool, d_pool);
    cudaGetSymbolAddress((void**)&p_cnt, d_cnt);

    float* out = (float*)d_out;

    // ---------------- fp16 conversion of GEMM inputs ----------------
    f2h_kernel<<<((N * F0 / 4) + 255) / 256, 256>>>((const float4*)x, (uint2*)p_x16, N * F0 / 4);
    f2h_kernel<<<((F0 * F1 / 4) + 255) / 256, 256>>>((const float4*)W1, (uint2*)p_w1h, F0 * F1 / 4);
    f2h_kernel<<<((F1 * F2 / 4) + 255) / 256, 256>>>((const float4*)W2, (uint2*)p_w2h, F1 * F2 / 4);

    // ---------------- CSR build (shared by both layers) ----------------
    cudaMemsetAsync(p_deg, 0, (size_t)N * sizeof(int));
    hist_kernel<<<(ET + 255) / 256, 256>>>(ei, p_deg, E, N);
    scan_kernel<<<1, 1024>>>(p_deg, p_rowptr, p_rowpos, N);
    scatter_kernel<<<(ET + 255) / 256, 256>>>(ei, p_rowpos, p_csrsrc, E, N);

    // ---------------- layer 1 ----------------
    {
        dim3 grid((N + 127) / 128, F1 / 64);
        gemm_f16<<<grid, 256>>>(p_x16, p_w1h, p_h1, N, F1, F0);
    }
    alpha_kernel<C1><<<(N * NHEAD + 255) / 256, 256>>>(p_h1, a_src1, a_dst1, p_as, p_ad, N);
    agg1_kernel<<<(N * 32 + 255) / 256, 256>>>(p_rowptr, p_csrsrc, p_as, p_ad,
                                               p_h1, b1, p_g1h, N);

    // ---------------- layer 2 ----------------
    {
        dim3 grid((N + 127) / 128, F2 / 64);
        gemm_f16<<<grid, 256>>>(p_g1h, p_w2h, p_h2, N, F2, F1);
    }
    alpha_kernel<C2><<<(N * NHEAD + 255) / 256, 256>>>(p_h2, a_src2, a_dst2, p_as, p_ad, N);
    agg2_kernel<<<(N * 32 + 255) / 256, 256>>>(p_rowptr, p_csrsrc, p_as, p_ad,
                                               p_h2, b2, p_g2, N);

    // ---------------- pooling + FC ----------------
    cudaMemsetAsync(p_pool, 0, (size_t)NG * F2 * sizeof(float));
    cudaMemsetAsync(p_cnt, 0, (size_t)NG * sizeof(float));
    {
        int nthreads = (N + 63) / 64;
        dim3 grid((nthreads + 127) / 128, F2);
        pool_kernel<<<grid, 128>>>(p_g2, batch, p_pool, N);
        count_kernel<<<(nthreads + 127) / 128, 128>>>(batch, p_cnt, N);
    }
    fc_kernel<<<NG, NOUT>>>(p_pool, p_cnt, fcw, fcb, out);
}

// round 12
// speedup vs baseline: 2.4199x; 1.2010x over previous
#include <cuda_runtime.h>
#include <cuda_fp16.h>
#include <cstdint>

// ---------------- problem constants (fixed by setup_inputs) ----------------
#define NN   50000
#define EE   800000
#define ET_MAX (EE+NN)
#define F0   128
#define NHEAD 4
#define C1   64
#define F1   (NHEAD*C1)   // 256
#define C2   16
#define F2   (NHEAD*C2)   // 64
#define NG   64
#define NOUT 32
#define NEG_SLOPE 0.2f

// ---------------- scratch (device globals; no allocation allowed) ----------
__device__ __half d_x16[NN*F0];
__device__ __half d_w1h[F0*F1];
__device__ __half d_w2h[F1*F2];
__device__ __half d_h1[NN*F1];
__device__ __half d_g1h[NN*F1];
__device__ __half d_h2[NN*F2];
__device__ float  d_g2[NN*F2];
__device__ float  d_as[NN*NHEAD];
__device__ float  d_ad[NN*NHEAD];
__device__ int    d_deg[NN];
__device__ int    d_rowptr[NN+1];
__device__ int    d_rowpos[NN];
__device__ int    d_csrsrc[ET_MAX];
__device__ float  d_pool[NG*F2];
__device__ float  d_cnt[NG];

// ---------------- helpers ---------------------------------------------------
__device__ __forceinline__ void cp_async16(void* smem, const void* gmem) {
    uint32_t s = (uint32_t)__cvta_generic_to_shared(smem);
    asm volatile("cp.async.ca.shared.global [%0], [%1], 16;" :: "r"(s), "l"(gmem));
}
__device__ __forceinline__ void cp_commit() { asm volatile("cp.async.commit_group;"); }
__device__ __forceinline__ void cp_wait0()  { asm volatile("cp.async.wait_group 0;"); }

__device__ __forceinline__ uint32_t smem_u32(const void* p) {
    return (uint32_t)__cvta_generic_to_shared(p);
}
__device__ __forceinline__ void ldsm_x4(uint32_t& r0, uint32_t& r1, uint32_t& r2, uint32_t& r3,
                                        uint32_t addr) {
    asm volatile("ldmatrix.sync.aligned.m8n8.x4.shared.b16 {%0,%1,%2,%3}, [%4];"
                 : "=r"(r0), "=r"(r1), "=r"(r2), "=r"(r3) : "r"(addr));
}
__device__ __forceinline__ void ldsm_x4_t(uint32_t& r0, uint32_t& r1, uint32_t& r2, uint32_t& r3,
                                          uint32_t addr) {
    asm volatile("ldmatrix.sync.aligned.m8n8.x4.trans.shared.b16 {%0,%1,%2,%3}, [%4];"
                 : "=r"(r0), "=r"(r1), "=r"(r2), "=r"(r3) : "r"(addr));
}
__device__ __forceinline__ void mma_f16(float* d, uint32_t a0, uint32_t a1, uint32_t a2,
                                        uint32_t a3, uint32_t b0, uint32_t b1) {
    asm volatile(
        "mma.sync.aligned.m16n8k16.row.col.f32.f16.f16.f32 "
        "{%0,%1,%2,%3}, {%4,%5,%6,%7}, {%8,%9}, {%0,%1,%2,%3};"
        : "+f"(d[0]), "+f"(d[1]), "+f"(d[2]), "+f"(d[3])
        : "r"(a0), "r"(a1), "r"(a2), "r"(a3), "r"(b0), "r"(b1));
}

// ---------------- fp32 -> fp16 convert (4 elems/thread) ---------------------
__global__ void f2h_kernel(const float4* __restrict__ in, uint2* __restrict__ out, int n4) {
    int i = blockIdx.x * blockDim.x + threadIdx.x;
    if (i >= n4) return;
    float4 v = in[i];
    __half2 a = __floats2half2_rn(v.x, v.y);
    __half2 b = __floats2half2_rn(v.z, v.w);
    uint2 o;
    o.x = *reinterpret_cast<uint32_t*>(&a);
    o.y = *reinterpret_cast<uint32_t*>(&b);
    out[i] = o;
}

// ---------------- fp16 HMMA GEMM (cp.async double-buffered, ldmatrix) ------
__global__ __launch_bounds__(256) void gemm_f16(
    const __half* __restrict__ A, const __half* __restrict__ B,
    __half* __restrict__ C, int M, int N, int K)
{
    __shared__ __half As[2][128][40];
    __shared__ __half Bs[2][32][72];

    int tid  = threadIdx.x;
    int warp = tid >> 5, lane = tid & 31;
    int wm = (warp & 3) * 32;
    int wn = (warp >> 2) * 32;
    int m0 = blockIdx.x * 128;
    int n0 = blockIdx.y * 64;

    int r  = lane >> 2;
    int cg = lane & 3;
    int g  = lane >> 3;
    int lr = lane & 7;
    int rowoff = (g & 1) * 8 + lr;
    int coloff = (g >> 1) * 8;

    int arow = tid >> 2;
    int akc  = (tid & 3) * 8;
    int brow = tid >> 3;
    int bnc  = (tid & 7) * 8;

    float acc[2][4][4];
#pragma unroll
    for (int i = 0; i < 2; i++)
#pragma unroll
        for (int j = 0; j < 4; j++)
#pragma unroll
            for (int q = 0; q < 4; q++) acc[i][j][q] = 0.f;

    int nk = K >> 5;

    {
        int gm0 = m0 + arow;       if (gm0 > M - 1) gm0 = M - 1;
        int gm1 = m0 + arow + 64;  if (gm1 > M - 1) gm1 = M - 1;
        cp_async16(&As[0][arow     ][akc], &A[(size_t)gm0 * K + akc]);
        cp_async16(&As[0][arow + 64][akc], &A[(size_t)gm1 * K + akc]);
        cp_async16(&Bs[0][brow][bnc], &B[(size_t)brow * N + n0 + bnc]);
        cp_commit();
    }

    for (int t = 0; t < nk; t++) {
        cp_wait0();
        __syncthreads();
        int buf = t & 1;

        if (t + 1 < nk) {
            int k0 = (t + 1) << 5;
            int gm0 = m0 + arow;       if (gm0 > M - 1) gm0 = M - 1;
            int gm1 = m0 + arow + 64;  if (gm1 > M - 1) gm1 = M - 1;
            cp_async16(&As[buf ^ 1][arow     ][akc], &A[(size_t)gm0 * K + k0 + akc]);
            cp_async16(&As[buf ^ 1][arow + 64][akc], &A[(size_t)gm1 * K + k0 + akc]);
            cp_async16(&Bs[buf ^ 1][brow][bnc], &B[(size_t)(k0 + brow) * N + n0 + bnc]);
            cp_commit();
        }

#pragma unroll
        for (int ks = 0; ks < 32; ks += 16) {
            uint32_t a[2][4];
#pragma unroll
            for (int mt = 0; mt < 2; mt++)
                ldsm_x4(a[mt][0], a[mt][1], a[mt][2], a[mt][3],
                        smem_u32(&As[buf][wm + mt * 16 + rowoff][ks + coloff]));
            uint32_t b[4][2];
#pragma unroll
            for (int np = 0; np < 2; np++) {
                uint32_t r0, r1, r2, r3;
                ldsm_x4_t(r0, r1, r2, r3,
                          smem_u32(&Bs[buf][ks + rowoff][wn + np * 16 + coloff]));
                b[np * 2][0] = r0; b[np * 2][1] = r1;
                b[np * 2 + 1][0] = r2; b[np * 2 + 1][1] = r3;
            }
#pragma unroll
            for (int mt = 0; mt < 2; mt++)
#pragma unroll
                for (int nt = 0; nt < 4; nt++)
                    mma_f16(acc[mt][nt], a[mt][0], a[mt][1], a[mt][2], a[mt][3],
                            b[nt][0], b[nt][1]);
        }
        __syncthreads();
    }

#pragma unroll
    for (int mt = 0; mt < 2; mt++) {
#pragma unroll
        for (int nt = 0; nt < 4; nt++) {
            int row = m0 + wm + mt * 16 + r;
            int col = n0 + wn + nt * 8 + 2 * cg;
            if (row < M) {
                __half2 o = __floats2half2_rn(acc[mt][nt][0], acc[mt][nt][1]);
                *reinterpret_cast<__half2*>(&C[(size_t)row * N + col]) = o;
            }
            if (row + 8 < M) {
                __half2 o = __floats2half2_rn(acc[mt][nt][2], acc[mt][nt][3]);
                *reinterpret_cast<__half2*>(&C[(size_t)(row + 8) * N + col]) = o;
            }
        }
    }
}

// ---------------- CSR build: histogram -> scan -> scatter -------------------
__global__ void hist_kernel(const int* __restrict__ ei, int* __restrict__ deg,
                            int E, int N) {
    int e = blockIdx.x * blockDim.x + threadIdx.x;
    if (e >= E + N) return;
    int d = (e < E) ? ei[E + e] : (e - E);
    atomicAdd(&deg[d], 1);
}

__global__ void scan_kernel(const int* __restrict__ deg, int* __restrict__ rowptr,
                            int* __restrict__ rowpos, int N) {
    __shared__ int sums[1024];
    int t = threadIdx.x;
    int CH = (N + 1023) / 1024;
    int b = t * CH, e = min(N, b + CH);
    int s = 0;
    for (int i = b; i < e; i++) s += deg[i];
    sums[t] = s;
    __syncthreads();
    for (int off = 1; off < 1024; off <<= 1) {
        int v = (t >= off) ? sums[t - off] : 0;
        __syncthreads();
        sums[t] += v;
        __syncthreads();
    }
    int run = (t == 0) ? 0 : sums[t - 1];
    for (int i = b; i < e; i++) {
        rowptr[i] = run;
        rowpos[i] = run;
        run += deg[i];
    }
    if (t == 1023) rowptr[N] = sums[1023];
}

__global__ void scatter_kernel(const int* __restrict__ ei, int* __restrict__ rowpos,
                               int* __restrict__ csrsrc, int E, int N) {
    int e = blockIdx.x * blockDim.x + threadIdx.x;
    if (e >= E + N) return;
    int s, d;
    if (e < E) { s = ei[e]; d = ei[E + e]; } else { s = d = e - E; }
    int pos = atomicAdd(&rowpos[d], 1);
    csrsrc[pos] = s;
}

// ---------------- per-node attention logits (fp16 features) ----------------
template<int C>
__global__ void alpha_kernel(const __half* __restrict__ h,
                             const float* __restrict__ asr, const float* __restrict__ adt,
                             float* __restrict__ outs, float* __restrict__ outd, int N) {
    int idx = blockIdx.x * blockDim.x + threadIdx.x;
    if (idx >= N * NHEAD) return;
    int hh = idx & (NHEAD - 1);
    const __half* hp = h + (size_t)idx * C;
    const float* ap = asr + hh * C;
    const float* dp = adt + hh * C;
    float ss = 0.f, dd = 0.f;
#pragma unroll
    for (int i = 0; i < C; i += 8) {
        uint4 raw = *reinterpret_cast<const uint4*>(hp + i);
        float2 f0 = __half22float2(*reinterpret_cast<__half2*>(&raw.x));
        float2 f1 = __half22float2(*reinterpret_cast<__half2*>(&raw.y));
        float2 f2 = __half22float2(*reinterpret_cast<__half2*>(&raw.z));
        float2 f3 = __half22float2(*reinterpret_cast<__half2*>(&raw.w));
        float4 a0 = *reinterpret_cast<const float4*>(ap + i);
        float4 a1 = *reinterpret_cast<const float4*>(ap + i + 4);
        float4 d0 = *reinterpret_cast<const float4*>(dp + i);
        float4 d1 = *reinterpret_cast<const float4*>(dp + i + 4);
        ss += f0.x * a0.x + f0.y * a0.y + f1.x * a0.z + f1.y * a0.w
            + f2.x * a1.x + f2.y * a1.y + f3.x * a1.z + f3.y * a1.w;
        dd += f0.x * d0.x + f0.y * d0.y + f1.x * d0.z + f1.y * d0.w
            + f2.x * d1.x + f2.y * d1.y + f3.x * d1.z + f3.y * d1.w;
    }
    outs[idx] = ss;
    outd[idx] = dd;
}

// ---------------- pull aggregation layer 1 (warp per dst, all heads) -------
// 2x edge unroll for MLP. Lane owns 8 channels; head = lane>>3.
__global__ void agg1_kernel(const int* __restrict__ rowptr, const int* __restrict__ csrsrc,
                            const float* __restrict__ as, const float* __restrict__ ad,
                            const __half* __restrict__ h,
                            const float* __restrict__ bias, __half* __restrict__ out, int N) {
    int gw = (blockIdx.x * blockDim.x + threadIdx.x) >> 5;
    int lane = threadIdx.x & 31;
    if (gw >= N) return;
    int hh = lane >> 3;
    int beg = rowptr[gw], end = rowptr[gw + 1];
    float adh = ad[(size_t)gw * 4 + hh];
    float4 acc0 = make_float4(0.f, 0.f, 0.f, 0.f);
    float4 acc1 = make_float4(0.f, 0.f, 0.f, 0.f);
    float wsum = 0.f;
    int i = beg;
    for (; i + 1 < end; i += 2) {
        int s0 = csrsrc[i], s1 = csrsrc[i + 1];
        float as0 = as[(size_t)s0 * 4 + hh];
        float as1 = as[(size_t)s1 * 4 + hh];
        uint4 ra = *reinterpret_cast<const uint4*>(h + (size_t)s0 * F1 + lane * 8);
        uint4 rb = *reinterpret_cast<const uint4*>(h + (size_t)s1 * F1 + lane * 8);
        float t0 = as0 + adh; t0 = t0 > 0.f ? t0 : NEG_SLOPE * t0;
        float t1 = as1 + adh; t1 = t1 > 0.f ? t1 : NEG_SLOPE * t1;
        float w0 = __expf(t0), w1 = __expf(t1);
        wsum += w0 + w1;
        float2 f;
        f = __half22float2(*reinterpret_cast<__half2*>(&ra.x)); acc0.x += w0 * f.x; acc0.y += w0 * f.y;
        f = __half22float2(*reinterpret_cast<__half2*>(&ra.y)); acc0.z += w0 * f.x; acc0.w += w0 * f.y;
        f = __half22float2(*reinterpret_cast<__half2*>(&ra.z)); acc1.x += w0 * f.x; acc1.y += w0 * f.y;
        f = __half22float2(*reinterpret_cast<__half2*>(&ra.w)); acc1.z += w0 * f.x; acc1.w += w0 * f.y;
        f = __half22float2(*reinterpret_cast<__half2*>(&rb.x)); acc0.x += w1 * f.x; acc0.y += w1 * f.y;
        f = __half22float2(*reinterpret_cast<__half2*>(&rb.y)); acc0.z += w1 * f.x; acc0.w += w1 * f.y;
        f = __half22float2(*reinterpret_cast<__half2*>(&rb.z)); acc1.x += w1 * f.x; acc1.y += w1 * f.y;
        f = __half22float2(*reinterpret_cast<__half2*>(&rb.w)); acc1.z += w1 * f.x; acc1.w += w1 * f.y;
    }
    if (i < end) {
        int s0 = csrsrc[i];
        float as0 = as[(size_t)s0 * 4 + hh];
        float t0 = as0 + adh; t0 = t0 > 0.f ? t0 : NEG_SLOPE * t0;
        float w0 = __expf(t0);
        wsum += w0;
        uint4 ra = *reinterpret_cast<const uint4*>(h + (size_t)s0 * F1 + lane * 8);
        float2 f;
        f = __half22float2(*reinterpret_cast<__half2*>(&ra.x)); acc0.x += w0 * f.x; acc0.y += w0 * f.y;
        f = __half22float2(*reinterpret_cast<__half2*>(&ra.y)); acc0.z += w0 * f.x; acc0.w += w0 * f.y;
        f = __half22float2(*reinterpret_cast<__half2*>(&ra.z)); acc1.x += w0 * f.x; acc1.y += w0 * f.y;
        f = __half22float2(*reinterpret_cast<__half2*>(&ra.w)); acc1.z += w0 * f.x; acc1.w += w0 * f.y;
    }
    float inv = 1.f / wsum;
    int c = lane * 8;
    const float4* bp = reinterpret_cast<const float4*>(bias + c);
    float4 b0 = bp[0], b1 = bp[1];
    __half2 p0 = __floats2half2_rn(fmaxf(acc0.x * inv + b0.x, 0.f), fmaxf(acc0.y * inv + b0.y, 0.f));
    __half2 p1 = __floats2half2_rn(fmaxf(acc0.z * inv + b0.z, 0.f), fmaxf(acc0.w * inv + b0.w, 0.f));
    __half2 p2 = __floats2half2_rn(fmaxf(acc1.x * inv + b1.x, 0.f), fmaxf(acc1.y * inv + b1.y, 0.f));
    __half2 p3 = __floats2half2_rn(fmaxf(acc1.z * inv + b1.z, 0.f), fmaxf(acc1.w * inv + b1.w, 0.f));
    uint4 o;
    o.x = *reinterpret_cast<uint32_t*>(&p0);
    o.y = *reinterpret_cast<uint32_t*>(&p1);
    o.z = *reinterpret_cast<uint32_t*>(&p2);
    o.w = *reinterpret_cast<uint32_t*>(&p3);
    *reinterpret_cast<uint4*>(out + (size_t)gw * F1 + c) = o;
}

// ---------------- pull aggregation layer 2 (warp per dst node) -------------
__global__ void agg2_kernel(const int* __restrict__ rowptr, const int* __restrict__ csrsrc,
                            const float* __restrict__ as, const float* __restrict__ ad,
                            const __half* __restrict__ h,
                            const float* __restrict__ bias, float* __restrict__ out, int N) {
    int gw = (blockIdx.x * blockDim.x + threadIdx.x) >> 5;
    int lane = threadIdx.x & 31;
    if (gw >= N) return;
    int hh = lane >> 3;
    int beg = rowptr[gw], end = rowptr[gw + 1];
    float adh = ad[(size_t)gw * 4 + hh];
    float acc0 = 0.f, acc1 = 0.f, wsum = 0.f;
    int i = beg;
    for (; i + 1 < end; i += 2) {
        int s0 = csrsrc[i], s1 = csrsrc[i + 1];
        float as0 = as[(size_t)s0 * 4 + hh];
        float as1 = as[(size_t)s1 * 4 + hh];
        __half2 hv0 = *reinterpret_cast<const __half2*>(h + (size_t)s0 * F2 + lane * 2);
        __half2 hv1 = *reinterpret_cast<const __half2*>(h + (size_t)s1 * F2 + lane * 2);
        float t0 = as0 + adh; t0 = t0 > 0.f ? t0 : NEG_SLOPE * t0;
        float t1 = as1 + adh; t1 = t1 > 0.f ? t1 : NEG_SLOPE * t1;
        float w0 = __expf(t0), w1 = __expf(t1);
        wsum += w0 + w1;
        float2 v0 = __half22float2(hv0), v1 = __half22float2(hv1);
        acc0 += w0 * v0.x + w1 * v1.x;
        acc1 += w0 * v0.y + w1 * v1.y;
    }
    if (i < end) {
        int s0 = csrsrc[i];
        float as0 = as[(size_t)s0 * 4 + hh];
        float t0 = as0 + adh; t0 = t0 > 0.f ? t0 : NEG_SLOPE * t0;
        float w0 = __expf(t0);
        wsum += w0;
        float2 v0 = __half22float2(*reinterpret_cast<const __half2*>(h + (size_t)s0 * F2 + lane * 2));
        acc0 += w0 * v0.x;
        acc1 += w0 * v0.y;
    }
    float inv = 1.f / wsum;
    int c = lane * 2;
    float o0 = acc0 * inv + bias[c];
    float o1 = acc1 * inv + bias[c + 1];
    float2 o = make_float2(o0 > 0.f ? o0 : 0.f, o1 > 0.f ? o1 : 0.f);
    *reinterpret_cast<float2*>(out + (size_t)gw * F2 + c) = o;
}

// ---------------- pooling (batch sorted -> run-length accumulation) --------
__global__ void pool_kernel(const float* __restrict__ g, const int* __restrict__ batch,
                            float* __restrict__ pool, int N) {
    int c = blockIdx.y;
    int t = blockIdx.x * blockDim.x + threadIdx.x;
    const int CH = 64;
    int n0 = t * CH;
    if (n0 >= N) return;
    int n1 = min(N, n0 + CH);
    int cur = batch[n0];
    float acc = 0.f;
    for (int n = n0; n < n1; n++) {
        int bb = batch[n];
        if (bb != cur) { atomicAdd(&pool[cur * F2 + c], acc); cur = bb; acc = 0.f; }
        acc += g[(size_t)n * F2 + c];
    }
    atomicAdd(&pool[cur * F2 + c], acc);
}

__global__ void count_kernel(const int* __restrict__ batch, float* __restrict__ cnt, int N) {
    int t = blockIdx.x * blockDim.x + threadIdx.x;
    const int CH = 64;
    int n0 = t * CH;
    if (n0 >= N) return;
    int n1 = min(N, n0 + CH);
    int cur = batch[n0];
    float acc = 0.f;
    for (int n = n0; n < n1; n++) {
        int bb = batch[n];
        if (bb != cur) { atomicAdd(&cnt[cur], acc); cur = bb; acc = 0.f; }
        acc += 1.f;
    }
    atomicAdd(&cnt[cur], acc);
}

// ---------------- final FC --------------------------------------------------
__global__ void fc_kernel(const float* __restrict__ pool, const float* __restrict__ cnt,
                          const float* __restrict__ w, const float* __restrict__ b,
                          float* __restrict__ out) {
    int g = blockIdx.x;
    int j = threadIdx.x;
    float inv = 1.f / fmaxf(cnt[g], 1.f);
    float acc = b[j];
#pragma unroll
    for (int c = 0; c < F2; c++)
        acc += pool[g * F2 + c] * inv * w[c * NOUT + j];
    out[g * NOUT + j] = acc;
}

// ---------------- launch ----------------------------------------------------
extern "C" void kernel_launch(void* const* d_in, const int* in_sizes, int n_in,
                              void* d_out, int out_size) {
    const float* x      = (const float*)d_in[0];
    const int*   ei     = (const int*)  d_in[1];
    const int*   batch  = (const int*)  d_in[2];
    const float* W1     = (const float*)d_in[3];
    const float* a_src1 = (const float*)d_in[4];
    const float* a_dst1 = (const float*)d_in[5];
    const float* b1     = (const float*)d_in[6];
    const float* W2     = (const float*)d_in[7];
    const float* a_src2 = (const float*)d_in[8];
    const float* a_dst2 = (const float*)d_in[9];
    const float* b2     = (const float*)d_in[10];
    const float* fcw    = (const float*)d_in[11];
    const float* fcb    = (const float*)d_in[12];

    int N = in_sizes[0] / F0;     // 50000
    int E = in_sizes[1] / 2;      // 800000
    int ET = E + N;

    __half *p_x16, *p_w1h, *p_w2h, *p_h1, *p_g1h, *p_h2;
    float *p_g2, *p_as, *p_ad, *p_pool, *p_cnt;
    int *p_deg, *p_rowptr, *p_rowpos, *p_csrsrc;
    cudaGetSymbolAddress((void**)&p_x16, d_x16);
    cudaGetSymbolAddress((void**)&p_w1h, d_w1h);
    cudaGetSymbolAddress((void**)&p_w2h, d_w2h);
    cudaGetSymbolAddress((void**)&p_h1, d_h1);
    cudaGetSymbolAddress((void**)&p_g1h, d_g1h);
    cudaGetSymbolAddress((void**)&p_h2, d_h2);
    cudaGetSymbolAddress((void**)&p_g2, d_g2);
    cudaGetSymbolAddress((void**)&p_as, d_as);
    cudaGetSymbolAddress((void**)&p_ad, d_ad);
    cudaGetSymbolAddress((void**)&p_deg, d_deg);
    cudaGetSymbolAddress((void**)&p_rowptr, d_rowptr);
    cudaGetSymbolAddress((void**)&p_rowpos, d_rowpos);
    cudaGetSymbolAddress((void**)&p_csrsrc, d_csrsrc);
    cudaGetSymbolAddress((void**)&p_pool, d_pool);
    cudaGetSymbolAddress((void**)&p_cnt, d_cnt);

    float* out = (float*)d_out;

    // One-time stream/event creation (first call is the non-captured
    // correctness run; captured calls only record/wait -> identical work).
    static cudaStream_t s2 = nullptr;
    static cudaEvent_t ev_fork = nullptr, ev_join = nullptr;
    if (s2 == nullptr) {
        cudaStreamCreateWithFlags(&s2, cudaStreamNonBlocking);
        cudaEventCreateWithFlags(&ev_fork, cudaEventDisableTiming);
        cudaEventCreateWithFlags(&ev_join, cudaEventDisableTiming);
    }

    // ---- fork: CSR build + pooling init on s2 (depends only on ei/batch) ----
    cudaEventRecord(ev_fork, 0);
    cudaStreamWaitEvent(s2, ev_fork, 0);
    cudaMemsetAsync(p_deg, 0, (size_t)N * sizeof(int), s2);
    hist_kernel<<<(ET + 255) / 256, 256, 0, s2>>>(ei, p_deg, E, N);
    scan_kernel<<<1, 1024, 0, s2>>>(p_deg, p_rowptr, p_rowpos, N);
    scatter_kernel<<<(ET + 255) / 256, 256, 0, s2>>>(ei, p_rowpos, p_csrsrc, E, N);
    cudaMemsetAsync(p_pool, 0, (size_t)NG * F2 * sizeof(float), s2);
    cudaMemsetAsync(p_cnt, 0, (size_t)NG * sizeof(float), s2);
    count_kernel<<<(((N + 63) / 64) + 127) / 128, 128, 0, s2>>>(batch, p_cnt, N);
    cudaEventRecord(ev_join, s2);

    // ---- main stream: fp16 conversion + GEMM1 + alpha1 (independent) ----
    f2h_kernel<<<((N * F0 / 4) + 255) / 256, 256>>>((const float4*)x, (uint2*)p_x16, N * F0 / 4);
    f2h_kernel<<<((F0 * F1 / 4) + 255) / 256, 256>>>((const float4*)W1, (uint2*)p_w1h, F0 * F1 / 4);
    f2h_kernel<<<((F1 * F2 / 4) + 255) / 256, 256>>>((const float4*)W2, (uint2*)p_w2h, F1 * F2 / 4);
    {
        dim3 grid((N + 127) / 128, F1 / 64);
        gemm_f16<<<grid, 256>>>(p_x16, p_w1h, p_h1, N, F1, F0);
    }
    alpha_kernel<C1><<<(N * NHEAD + 255) / 256, 256>>>(p_h1, a_src1, a_dst1, p_as, p_ad, N);

    // ---- join: aggregation needs the CSR ----
    cudaStreamWaitEvent(0, ev_join, 0);
    agg1_kernel<<<(N * 32 + 255) / 256, 256>>>(p_rowptr, p_csrsrc, p_as, p_ad,
                                               p_h1, b1, p_g1h, N);

    // ---------------- layer 2 ----------------
    {
        dim3 grid((N + 127) / 128, F2 / 64);
        gemm_f16<<<grid, 256>>>(p_g1h, p_w2h, p_h2, N, F2, F1);
    }
    alpha_kernel<C2><<<(N * NHEAD + 255) / 256, 256>>>(p_h2, a_src2, a_dst2, p_as, p_ad, N);
    agg2_kernel<<<(N * 32 + 255) / 256, 256>>>(p_rowptr, p_csrsrc, p_as, p_ad,
                                               p_h2, b2, p_g2, N);

    // ---------------- pooling + FC ----------------
    {
        int nthreads = (N + 63) / 64;
        dim3 grid((nthreads + 127) / 128, F2);
        pool_kernel<<<grid, 128>>>(p_g2, batch, p_pool, N);
    }
    fc_kernel<<<NG, NOUT>>>(p_pool, p_cnt, fcw, fcb, out);
}